// round 13
// baseline (speedup 1.0000x reference)
#include <cuda_runtime.h>
#include <cuda_bf16.h>
#include <cstddef>
#include <cstdint>

// Problem constants
#define BB 512   // batch
#define TT 512   // timesteps
#define FF 64    // input features
#define H1 128   // layer1 hidden
#define G1 512   // 4*H1
#define H2 64    // layer2 hidden
#define G2 256   // 4*H2

typedef unsigned long long u64;

// ---------------------------------------------------------------------------
// Packed fp32x2 helpers
// ---------------------------------------------------------------------------
__device__ __forceinline__ u64 pack2(float lo, float hi) {
    u64 r; asm("mov.b64 %0, {%1, %2};" : "=l"(r) : "f"(lo), "f"(hi)); return r;
}
__device__ __forceinline__ float2 unpack2(u64 v) {
    float2 f; asm("mov.b64 {%0, %1}, %2;" : "=f"(f.x), "=f"(f.y) : "l"(v)); return f;
}
__device__ __forceinline__ void fma2(u64& d, u64 a, u64 b) {
    asm("fma.rn.f32x2 %0, %1, %2, %0;" : "+l"(d) : "l"(a), "l"(b));
}
__device__ __forceinline__ void add2(u64& d, u64 a) {
    asm("add.rn.f32x2 %0, %0, %1;" : "+l"(d) : "l"(a));
}

// ---------------------------------------------------------------------------
// Device scratch
// ---------------------------------------------------------------------------
__device__ float g_bp1[G1];
__device__ float g_Up1[H1 * G1];        // U1 permuted: [k][j*4+gate]
__device__ float g_bp2[G2];
__device__ float g_Up2[H2 * G2];
// Transposed stacked-K weights: [n][k'] with k' = [Wh | Wl | Wh]
__device__ __align__(16) __nv_bfloat16 g_Wt1[G1 * 3 * FF];   // [512][192]
__device__ __align__(16) __nv_bfloat16 g_Wt2[G2 * 3 * H1];   // [256][384]
__device__ float g_xw1[(size_t)TT * BB * G1];  // [t][b][j*4+gate]
__device__ float g_h1[(size_t)TT * BB * H1];   // [t][b][j]
__device__ float g_xw2[(size_t)TT * BB * G2];  // [t][b][j*4+gate]
__device__ float g_h2[BB * H2];                // final layer2 h

__device__ __forceinline__ float sigf(float x) {
    return __fdividef(1.0f, 1.0f + __expf(-x));
}

// ---------------------------------------------------------------------------
// Prep: permuted fp32 bias/U (n = j*4+gate, gate order i,f,g,o) + transposed
// stacked-K bf16 weights Wt[n][k'] with k' spans [Wh | Wl | Wh].
// ---------------------------------------------------------------------------
__global__ void prep_kernel(const float* __restrict__ W1, const float* __restrict__ U1,
                            const float* __restrict__ b1, const float* __restrict__ W2,
                            const float* __restrict__ U2, const float* __restrict__ b2)
{
    int i = blockIdx.x * blockDim.x + threadIdx.x;
    if (i < G1) {
        int j = i >> 2, gi = i & 3;
        g_bp1[i] = b1[gi * H1 + j];
    }
    if (i < H1 * G1) {
        int k = i >> 9, n = i & 511;
        int j = n >> 2, gi = n & 3;
        g_Up1[i] = U1[k * G1 + gi * H1 + j];
    }
    if (i < G2) {
        int j = i >> 2, gi = i & 3;
        g_bp2[i] = b2[gi * H2 + j];
    }
    if (i < H2 * G2) {
        int k = i >> 8, n = i & 255;
        int j = n >> 2, gi = n & 3;
        g_Up2[i] = U2[k * G2 + gi * H2 + j];
    }
    if (i < G1 * 3 * FF) {   // Wt1[n][kp], n in [0,512), kp in [0,192)
        int n = i / 192, kp = i - n * 192;
        int p = kp / FF, ks = kp - p * FF;
        float v = W1[ks * G1 + (n & 3) * H1 + (n >> 2)];
        __nv_bfloat16 h = __float2bfloat16(v);
        g_Wt1[i] = (p == 1) ? __float2bfloat16(v - __bfloat162float(h)) : h;
    }
    if (i < G2 * 3 * H1) {   // Wt2[n][kp], n in [0,256), kp in [0,384)
        int n = i / 384, kp = i - n * 384;
        int p = kp / H1, ks = kp - p * H1;
        float v = W2[ks * G2 + (n & 3) * H2 + (n >> 2)];
        __nv_bfloat16 h = __float2bfloat16(v);
        g_Wt2[i] = (p == 1) ? __float2bfloat16(v - __bfloat162float(h)) : h;
    }
}

// ---------------------------------------------------------------------------
// Tensor-core GEMM via mma.sync m16n8k16 bf16 (fp32 acc), stacked-K hi/lo.
// (proven R12 kernel, unchanged)
// ---------------------------------------------------------------------------
#define GMMA_SMEM (128 * 80 + 128 * 80)   // 20480 B

__global__ __launch_bounds__(256, 2) void gemm_mma(
    const float* __restrict__ A, const __nv_bfloat16* __restrict__ Wt,
    const float* __restrict__ bias, float* __restrict__ C,
    int sT, int sB, int K, int Kcat, int Ntot)
{
    extern __shared__ char smb[];
    __nv_bfloat16* As = (__nv_bfloat16*)smb;            // [128][40]
    __nv_bfloat16* Bs = (__nv_bfloat16*)(smb + 10240);  // [128][40]
    const int tid = threadIdx.x, lane = tid & 31, wid = tid >> 5;
    const int wm = wid & 1, wn = wid >> 1;
    const int grp = lane >> 2;          // 0..7
    const int qc  = lane & 3;           // 0..3
    const int mt = blockIdx.x << 7, nt = blockIdx.y << 7;

    float acc[4][4][4];
#pragma unroll
    for (int mi = 0; mi < 4; mi++)
#pragma unroll
        for (int ni = 0; ni < 4; ni++)
#pragma unroll
            for (int q = 0; q < 4; q++) acc[mi][ni][q] = 0.f;

    const int r = tid >> 1, hf = tid & 1;
    const int gm = mt + r;
    const int t0 = gm >> 9, b0 = gm & 511;
    const float* arow = A + (size_t)t0 * sT + (size_t)b0 * sB;

    const int nchunks = Kcat >> 5;
    for (int c = 0; c < nchunks; c++) {
        {   // ---- A: 16 fp32 -> bf16 (hi or lo half) ----
            int kbase = (c << 5) + (hf << 4);
            int lo = (kbase >= (K << 1));
            int ksrc = kbase; if (ksrc >= K) ksrc -= K; if (ksrc >= K) ksrc -= K;
            float4 v0 = *(const float4*)(arow + ksrc);
            float4 v1 = *(const float4*)(arow + ksrc + 4);
            float4 v2 = *(const float4*)(arow + ksrc + 8);
            float4 v3 = *(const float4*)(arow + ksrc + 12);
            float f[16] = {v0.x, v0.y, v0.z, v0.w, v1.x, v1.y, v1.z, v1.w,
                           v2.x, v2.y, v2.z, v2.w, v3.x, v3.y, v3.z, v3.w};
            unsigned o[8];
#pragma unroll
            for (int q = 0; q < 8; q++) {
                __nv_bfloat16 h0 = __float2bfloat16(f[2 * q]);
                __nv_bfloat16 h1 = __float2bfloat16(f[2 * q + 1]);
                if (lo) {
                    h0 = __float2bfloat16(f[2 * q] - __bfloat162float(h0));
                    h1 = __float2bfloat16(f[2 * q + 1] - __bfloat162float(h1));
                }
                o[q] = (unsigned)__bfloat16_as_ushort(h0) |
                       ((unsigned)__bfloat16_as_ushort(h1) << 16);
            }
            uint4* dst = (uint4*)((char*)As + r * 80 + hf * 32);
            dst[0] = make_uint4(o[0], o[1], o[2], o[3]);
            dst[1] = make_uint4(o[4], o[5], o[6], o[7]);
        }
        {   // ---- B: Wt[n][k'] slice, raw 16B copies ----
            int n = tid >> 1, s0 = tid & 1;
            const __nv_bfloat16* src = Wt + (size_t)(nt + n) * Kcat + (c << 5);
#pragma unroll
            for (int s = 0; s < 2; s++) {
                int seg = s0 + (s << 1);
                *(uint4*)((char*)Bs + n * 80 + seg * 16) =
                    *(const uint4*)(src + (seg << 3));
            }
        }
        __syncthreads();
#pragma unroll
        for (int ks = 0; ks < 2; ks++) {
            const int kofs = (ks << 4) + (qc << 1);
            uint32_t af[4][4];
#pragma unroll
            for (int mi = 0; mi < 4; mi++) {
                const __nv_bfloat16* ar0 = As + (wm * 64 + mi * 16 + grp) * 40 + kofs;
                af[mi][0] = *(const uint32_t*)(ar0);
                af[mi][1] = *(const uint32_t*)(ar0 + 8 * 40);
                af[mi][2] = *(const uint32_t*)(ar0 + 8);
                af[mi][3] = *(const uint32_t*)(ar0 + 8 * 40 + 8);
            }
            uint32_t bf[4][2];
#pragma unroll
            for (int ni = 0; ni < 4; ni++) {
                const __nv_bfloat16* br0 = Bs + (wn * 32 + ni * 8 + grp) * 40 + kofs;
                bf[ni][0] = *(const uint32_t*)(br0);
                bf[ni][1] = *(const uint32_t*)(br0 + 8);
            }
#pragma unroll
            for (int mi = 0; mi < 4; mi++)
#pragma unroll
                for (int ni = 0; ni < 4; ni++) {
                    asm volatile(
                        "mma.sync.aligned.m16n8k16.row.col.f32.bf16.bf16.f32 "
                        "{%0,%1,%2,%3}, {%4,%5,%6,%7}, {%8,%9}, {%0,%1,%2,%3};"
                        : "+f"(acc[mi][ni][0]), "+f"(acc[mi][ni][1]),
                          "+f"(acc[mi][ni][2]), "+f"(acc[mi][ni][3])
                        : "r"(af[mi][0]), "r"(af[mi][1]), "r"(af[mi][2]), "r"(af[mi][3]),
                          "r"(bf[ni][0]), "r"(bf[ni][1]));
                }
        }
        __syncthreads();
    }

#pragma unroll
    for (int mi = 0; mi < 4; mi++) {
        int r0 = mt + wm * 64 + mi * 16 + grp;
#pragma unroll
        for (int ni = 0; ni < 4; ni++) {
            int col = nt + wn * 32 + ni * 8 + (qc << 1);
            float b0v = __ldg(bias + col), b1v = __ldg(bias + col + 1);
            *(float2*)(C + (size_t)r0 * Ntot + col) =
                make_float2(acc[mi][ni][0] + b0v, acc[mi][ni][1] + b1v);
            *(float2*)(C + (size_t)(r0 + 8) * Ntot + col) =
                make_float2(acc[mi][ni][2] + b0v, acc[mi][ni][3] + b1v);
        }
    }
}

// ---------------------------------------------------------------------------
// Layer-1 recurrence, symmetric gate split. 128 CTAs x 256 threads.
// thread = (j in [0,128), ks in {0,1}); ks splits K=128 for the FMA phase
// (32 U rows smem + 32 in regs, as proven R4), but gates are SPLIT: half ks
// applies gates to batch rows {2ks, 2ks+1}. Each half writes the partner's
// two partial rows; both halves then combine + gate concurrently.
// ---------------------------------------------------------------------------
#define REC1_SMEM ((64 * 512 + 2 * 128 * 8 + 2 * 128 * 20) * 4)  // 159744 B

__global__ __launch_bounds__(256, 1) void rec1_kernel()
{
    extern __shared__ float sm[];
    float* Us = sm;                  // [64][512]
    float* hd = sm + 64 * 512;       // [2][128][8]
    float* ex = hd + 2 * 128 * 8;    // [2][128][20]: [writer half][j][...]

    const int tid  = threadIdx.x;
    const int j    = tid & 127;
    const int ks   = tid >> 7;
    const int brow = blockIdx.x << 2;
    const int myb  = brow + (ks << 1);   // first of this half's 2 batch rows

    for (int i = tid; i < 64 * 128; i += 256) {
        int s = i >> 7;
        int c = (i & 127) << 2;
        int krow = (s < 32) ? s : (s + 32);
        *(float4*)(Us + s * 512 + c) = *(const float4*)(g_Up1 + krow * 512 + c);
    }
    const int rbase = ks * 64 + 32;
    ulonglong2 uw[32];
#pragma unroll
    for (int r = 0; r < 32; r++)
        uw[r] = *(const ulonglong2*)(g_Up1 + (rbase + r) * 512 + (j << 2));
    for (int i = tid; i < 2 * 128 * 8; i += 256) hd[i] = 0.f;
    float cA = 0.f, cB = 0.f;
    __syncthreads();

    const float* up0 = Us + (ks * 32) * 512 + (j << 2);
    float* exw = ex + ks * 2560 + j * 20;              // my partials (for partner)
    const float* exr = ex + (ks ^ 1) * 2560 + j * 20;  // partner's partials (for me)
    const int ob = (ks ^ 1) << 1;                      // partner's first b
    const int mb = ks << 1;                            // my first b
    int buf = 0;
    for (int t = 0; t < TT; t++) {
        u64 z2[4][2];
#pragma unroll
        for (int b = 0; b < 4; b++) { z2[b][0] = 0ull; z2[b][1] = 0ull; }

        ulonglong2 xvA = *(const ulonglong2*)(g_xw1 + ((size_t)(t * BB + myb) << 9) + (j << 2));
        ulonglong2 xvB = *(const ulonglong2*)(g_xw1 + ((size_t)(t * BB + myb + 1) << 9) + (j << 2));

        const float* hb = hd + buf * 1024;
        {
            const float* hp = hb + (ks * 64) * 8;
            const float* up = up0;
#pragma unroll 4
            for (int r = 0; r < 32; r++) {
                ulonglong2 hA = *(const ulonglong2*)(hp + (r << 3));
                ulonglong2 hB = *(const ulonglong2*)(hp + (r << 3) + 4);
                ulonglong2 uv = *(const ulonglong2*)(up);
                up += 512;
                fma2(z2[0][0], hA.x, uv.x); fma2(z2[0][1], hA.x, uv.y);
                fma2(z2[1][0], hA.y, uv.x); fma2(z2[1][1], hA.y, uv.y);
                fma2(z2[2][0], hB.x, uv.x); fma2(z2[2][1], hB.x, uv.y);
                fma2(z2[3][0], hB.y, uv.x); fma2(z2[3][1], hB.y, uv.y);
            }
        }
        {
            const float* hp = hb + rbase * 8;
#pragma unroll
            for (int r = 0; r < 32; r++) {
                ulonglong2 hA = *(const ulonglong2*)(hp + (r << 3));
                ulonglong2 hB = *(const ulonglong2*)(hp + (r << 3) + 4);
                fma2(z2[0][0], hA.x, uw[r].x); fma2(z2[0][1], hA.x, uw[r].y);
                fma2(z2[1][0], hA.y, uw[r].x); fma2(z2[1][1], hA.y, uw[r].y);
                fma2(z2[2][0], hB.x, uw[r].x); fma2(z2[2][1], hB.x, uw[r].y);
                fma2(z2[3][0], hB.y, uw[r].x); fma2(z2[3][1], hB.y, uw[r].y);
            }
        }
        // write partials for partner's two rows
        *(ulonglong2*)(exw)     = make_ulonglong2(z2[ob][0],     z2[ob][1]);
        *(ulonglong2*)(exw + 4) = make_ulonglong2(z2[ob + 1][0], z2[ob + 1][1]);
        __syncthreads();
        // combine + gates for my two rows
        {
            ulonglong2 eA = *(const ulonglong2*)(exr);
            ulonglong2 eB = *(const ulonglong2*)(exr + 4);
            u64 zA0 = z2[mb][0], zA1 = z2[mb][1];
            add2(zA0, eA.x); add2(zA1, eA.y);
            add2(zA0, xvA.x); add2(zA1, xvA.y);
            u64 zB0 = z2[mb + 1][0], zB1 = z2[mb + 1][1];
            add2(zB0, eB.x); add2(zB1, eB.y);
            add2(zB0, xvB.x); add2(zB1, xvB.y);

            float2 pA0 = unpack2(zA0), pA1 = unpack2(zA1);
            float iA = sigf(pA0.x), fA = sigf(pA0.y);
            float gA = fmaxf(pA1.x, 0.f), oA = sigf(pA1.y);
            cA = fA * cA + iA * gA;
            float hvA = oA * fmaxf(cA, 0.f);

            float2 pB0 = unpack2(zB0), pB1 = unpack2(zB1);
            float iB = sigf(pB0.x), fB = sigf(pB0.y);
            float gB = fmaxf(pB1.x, 0.f), oB = sigf(pB1.y);
            cB = fB * cB + iB * gB;
            float hvB = oB * fmaxf(cB, 0.f);

            g_h1[((size_t)(t * BB + myb) << 7) + j] = hvA;
            g_h1[((size_t)(t * BB + myb + 1) << 7) + j] = hvB;
            float* hn = hd + (buf ^ 1) * 1024;
            *(ulonglong2*)(hn + (j << 3) + (ks << 2)) =
                make_ulonglong2(pack2(hvA, hvA), pack2(hvB, hvB));
        }
        __syncthreads();
        buf ^= 1;
    }
}

// ---------------------------------------------------------------------------
// Layer-2 recurrence, symmetric 4-way. 128 CTAs x 256 threads.
// thread = (j in [0,64), ks in [0,4)); ks splits K=64 for the FMA phase
// (8 smem rows + 8 reg rows, proven R4 layout), gates SPLIT: quarter ks
// applies gates to batch row brow+ks only.
// ---------------------------------------------------------------------------
#define REC2_SMEM ((32 * 256 + 2 * 64 * 8 + 4 * 64 * 20) * 4)  // 57856 B

__global__ __launch_bounds__(256, 1) void rec2_kernel()
{
    extern __shared__ float sm[];
    float* Us = sm;                  // [32][256]: s = q*8+r <-> krow = q*16+r
    float* hd = sm + 32 * 256;       // [2][64][8]
    float* ex = hd + 2 * 64 * 8;     // [4][64][20]: [writer quarter][j][b*4]

    const int tid  = threadIdx.x;
    const int j    = tid & 63;
    const int ks   = tid >> 6;       // 0..3
    const int brow = blockIdx.x << 2;
    const int myb  = brow + ks;

    for (int i = tid; i < 32 * 64; i += 256) {
        int s = i >> 6;
        int c = (i & 63) << 2;
        int krow = ((s >> 3) << 4) + (s & 7);
        *(float4*)(Us + s * 256 + c) = *(const float4*)(g_Up2 + krow * 256 + c);
    }
    const int rbase = (ks << 4) + 8;
    ulonglong2 uw[8];
#pragma unroll
    for (int r = 0; r < 8; r++)
        uw[r] = *(const ulonglong2*)(g_Up2 + (rbase + r) * 256 + (j << 2));
    for (int i = tid; i < 2 * 64 * 8; i += 256) hd[i] = 0.f;
    float cc = 0.f;
    __syncthreads();

    const float* up0 = Us + (ks << 3) * 256 + (j << 2);
    float* exw = ex + ks * 1280 + j * 20;
    int buf = 0;
    for (int t = 0; t < TT; t++) {
        u64 z2[4][2];
#pragma unroll
        for (int b = 0; b < 4; b++) { z2[b][0] = 0ull; z2[b][1] = 0ull; }

        ulonglong2 xv = *(const ulonglong2*)(g_xw2 + ((size_t)(t * BB + myb) << 8) + (j << 2));

        const float* hb = hd + buf * 512;
        {
            const float* hp = hb + (ks << 4) * 8;
            const float* up = up0;
#pragma unroll
            for (int r = 0; r < 8; r++) {
                ulonglong2 hA = *(const ulonglong2*)(hp + (r << 3));
                ulonglong2 hB = *(const ulonglong2*)(hp + (r << 3) + 4);
                ulonglong2 uv = *(const ulonglong2*)(up);
                up += 256;
                fma2(z2[0][0], hA.x, uv.x); fma2(z2[0][1], hA.x, uv.y);
                fma2(z2[1][0], hA.y, uv.x); fma2(z2[1][1], hA.y, uv.y);
                fma2(z2[2][0], hB.x, uv.x); fma2(z2[2][1], hB.x, uv.y);
                fma2(z2[3][0], hB.y, uv.x); fma2(z2[3][1], hB.y, uv.y);
            }
        }
        {
            const float* hp = hb + rbase * 8;
#pragma unroll
            for (int r = 0; r < 8; r++) {
                ulonglong2 hA = *(const ulonglong2*)(hp + (r << 3));
                ulonglong2 hB = *(const ulonglong2*)(hp + (r << 3) + 4);
                fma2(z2[0][0], hA.x, uw[r].x); fma2(z2[0][1], hA.x, uw[r].y);
                fma2(z2[1][0], hA.y, uw[r].x); fma2(z2[1][1], hA.y, uw[r].y);
                fma2(z2[2][0], hB.x, uw[r].x); fma2(z2[2][1], hB.x, uw[r].y);
                fma2(z2[3][0], hB.y, uw[r].x); fma2(z2[3][1], hB.y, uw[r].y);
            }
        }
        // write partials for other quarters' rows
#pragma unroll
        for (int b = 0; b < 4; b++)
            if (b != ks)
                *(ulonglong2*)(exw + (b << 2)) = make_ulonglong2(z2[b][0], z2[b][1]);
        __syncthreads();
        // combine partials for my row from the other 3 quarters
        {
            u64 z0 = z2[ks][0], z1 = z2[ks][1];
#pragma unroll
            for (int q = 0; q < 4; q++)
                if (q != ks) {
                    ulonglong2 e = *(const ulonglong2*)(ex + q * 1280 + j * 20 + (ks << 2));
                    add2(z0, e.x); add2(z1, e.y);
                }
            add2(z0, xv.x); add2(z1, xv.y);
            float2 p0 = unpack2(z0), p1 = unpack2(z1);
            float ig = sigf(p0.x), fg = sigf(p0.y);
            float gg = fmaxf(p1.x, 0.f), og = sigf(p1.y);
            cc = fg * cc + ig * gg;
            float hv = og * fmaxf(cc, 0.f);
            if (t == TT - 1) g_h2[(myb << 6) + j] = hv;
            float* hn = hd + (buf ^ 1) * 512;
            *(u64*)(hn + (j << 3) + (ks << 1)) = pack2(hv, hv);
        }
        __syncthreads();
        buf ^= 1;
    }
}

// ---------------------------------------------------------------------------
// Dense head
// ---------------------------------------------------------------------------
__global__ void dense_kernel(const float* __restrict__ Wd1, const float* __restrict__ bd1,
                             const float* __restrict__ Wd2, const float* __restrict__ bd2,
                             float* __restrict__ out)
{
    int b = blockIdx.x * blockDim.x + threadIdx.x;
    if (b >= BB) return;
    float h[H2];
#pragma unroll
    for (int k = 0; k < H2; k++) h[k] = g_h2[(b << 6) + k];
    float acc = bd2[0];
    for (int d = 0; d < 25; d++) {
        float s = bd1[d];
#pragma unroll
        for (int k = 0; k < H2; k++) s += h[k] * Wd1[k * 25 + d];
        acc += s * Wd2[d];
    }
    out[b] = acc;
}

// ---------------------------------------------------------------------------
// Launch
// ---------------------------------------------------------------------------
extern "C" void kernel_launch(void* const* d_in, const int* in_sizes, int n_in,
                              void* d_out, int out_size)
{
    const float* x   = (const float*)d_in[0];
    const float* W1  = (const float*)d_in[1];
    const float* U1  = (const float*)d_in[2];
    const float* b1  = (const float*)d_in[3];
    const float* W2  = (const float*)d_in[4];
    const float* U2  = (const float*)d_in[5];
    const float* b2  = (const float*)d_in[6];
    const float* Wd1 = (const float*)d_in[7];
    const float* bd1 = (const float*)d_in[8];
    const float* Wd2 = (const float*)d_in[9];
    const float* bd2 = (const float*)d_in[10];
    float* out = (float*)d_out;

    cudaFuncSetAttribute(rec1_kernel, cudaFuncAttributeMaxDynamicSharedMemorySize, REC1_SMEM);
    cudaFuncSetAttribute(rec2_kernel, cudaFuncAttributeMaxDynamicSharedMemorySize, REC2_SMEM);

    float *pbp1, *pbp2, *pxw1, *pxw2, *ph1;
    void *pWt1, *pWt2;
    cudaGetSymbolAddress((void**)&pbp1, g_bp1);
    cudaGetSymbolAddress((void**)&pbp2, g_bp2);
    cudaGetSymbolAddress((void**)&pxw1, g_xw1);
    cudaGetSymbolAddress((void**)&pxw2, g_xw2);
    cudaGetSymbolAddress((void**)&ph1,  g_h1);
    cudaGetSymbolAddress(&pWt1, g_Wt1);
    cudaGetSymbolAddress(&pWt2, g_Wt2);

    // 1. weight permute + transposed stacked-K bf16 images
    prep_kernel<<<512, 256>>>(W1, U1, b1, W2, U2, b2);

    // 2. xW1 (tensor cores): x @ W1 -> g_xw1[t][b][:]   (Kcat = 192)
    gemm_mma<<<dim3((TT * BB) / 128, G1 / 128), 256, GMMA_SMEM>>>(
        x, (const __nv_bfloat16*)pWt1, pbp1, pxw1, FF, TT * FF, FF, 3 * FF, G1);

    // 3. layer-1 recurrence -> g_h1[t][b][:]
    rec1_kernel<<<BB / 4, 256, REC1_SMEM>>>();

    // 4. xW2 (tensor cores): h1 @ W2 -> g_xw2[t][b][:]  (Kcat = 384)
    gemm_mma<<<dim3((TT * BB) / 128, G2 / 128), 256, GMMA_SMEM>>>(
        ph1, (const __nv_bfloat16*)pWt2, pbp2, pxw2, BB * H1, H1, H1, 3 * H1, G2);

    // 5. layer-2 recurrence -> g_h2[b][:]
    rec2_kernel<<<BB / 4, 256, REC2_SMEM>>>();

    // 6. dense head
    dense_kernel<<<2, 256>>>(Wd1, bd1, Wd2, bd2, out);
}

// round 15
// speedup vs baseline: 1.0593x; 1.0593x over previous
#include <cuda_runtime.h>
#include <cuda_bf16.h>
#include <cstddef>
#include <cstdint>

// Problem constants
#define BB 512   // batch
#define TT 512   // timesteps
#define FF 64    // input features
#define H1 128   // layer1 hidden
#define G1 512   // 4*H1
#define H2 64    // layer2 hidden
#define G2 256   // 4*H2

typedef unsigned long long u64;

// ---------------------------------------------------------------------------
// Packed fp32x2 helpers
// ---------------------------------------------------------------------------
__device__ __forceinline__ u64 pack2(float lo, float hi) {
    u64 r; asm("mov.b64 %0, {%1, %2};" : "=l"(r) : "f"(lo), "f"(hi)); return r;
}
__device__ __forceinline__ float2 unpack2(u64 v) {
    float2 f; asm("mov.b64 {%0, %1}, %2;" : "=f"(f.x), "=f"(f.y) : "l"(v)); return f;
}
__device__ __forceinline__ void fma2(u64& d, u64 a, u64 b) {
    asm("fma.rn.f32x2 %0, %1, %2, %0;" : "+l"(d) : "l"(a), "l"(b));
}
__device__ __forceinline__ void add2(u64& d, u64 a) {
    asm("add.rn.f32x2 %0, %0, %1;" : "+l"(d) : "l"(a));
}

// ---------------------------------------------------------------------------
// Device scratch
// ---------------------------------------------------------------------------
__device__ float g_bp1[G1];
__device__ float g_Up1[H1 * G1];        // U1 permuted: [k][j*4+gate]
__device__ float g_bp2[G2];
__device__ float g_Up2[H2 * G2];
// Transposed stacked-K weights: [n][k'] with k' = [Wh | Wl | Wh]
__device__ __align__(16) __nv_bfloat16 g_Wt1[G1 * 3 * FF];   // [512][192]
__device__ __align__(16) __nv_bfloat16 g_Wt2[G2 * 3 * H1];   // [256][384]
__device__ float g_xw1[(size_t)TT * BB * G1];  // [t][b][j*4+gate]
__device__ float g_h1[(size_t)TT * BB * H1];   // [t][b][j]
__device__ float g_xw2[(size_t)TT * BB * G2];  // [t][b][j*4+gate]
__device__ float g_h2[BB * H2];                // final layer2 h

__device__ __forceinline__ float sigf(float x) {
    return __fdividef(1.0f, 1.0f + __expf(-x));
}

// ---------------------------------------------------------------------------
// Prep: permuted fp32 bias/U (n = j*4+gate, gate order i,f,g,o) + transposed
// stacked-K bf16 weights Wt[n][k'] with k' spans [Wh | Wl | Wh].
// ---------------------------------------------------------------------------
__global__ void prep_kernel(const float* __restrict__ W1, const float* __restrict__ U1,
                            const float* __restrict__ b1, const float* __restrict__ W2,
                            const float* __restrict__ U2, const float* __restrict__ b2)
{
    int i = blockIdx.x * blockDim.x + threadIdx.x;
    if (i < G1) {
        int j = i >> 2, gi = i & 3;
        g_bp1[i] = b1[gi * H1 + j];
    }
    if (i < H1 * G1) {
        int k = i >> 9, n = i & 511;
        int j = n >> 2, gi = n & 3;
        g_Up1[i] = U1[k * G1 + gi * H1 + j];
    }
    if (i < G2) {
        int j = i >> 2, gi = i & 3;
        g_bp2[i] = b2[gi * H2 + j];
    }
    if (i < H2 * G2) {
        int k = i >> 8, n = i & 255;
        int j = n >> 2, gi = n & 3;
        g_Up2[i] = U2[k * G2 + gi * H2 + j];
    }
    if (i < G1 * 3 * FF) {   // Wt1[n][kp], n in [0,512), kp in [0,192)
        int n = i / 192, kp = i - n * 192;
        int p = kp / FF, ks = kp - p * FF;
        float v = W1[ks * G1 + (n & 3) * H1 + (n >> 2)];
        __nv_bfloat16 h = __float2bfloat16(v);
        g_Wt1[i] = (p == 1) ? __float2bfloat16(v - __bfloat162float(h)) : h;
    }
    if (i < G2 * 3 * H1) {   // Wt2[n][kp], n in [0,256), kp in [0,384)
        int n = i / 384, kp = i - n * 384;
        int p = kp / H1, ks = kp - p * H1;
        float v = W2[ks * G2 + (n & 3) * H2 + (n >> 2)];
        __nv_bfloat16 h = __float2bfloat16(v);
        g_Wt2[i] = (p == 1) ? __float2bfloat16(v - __bfloat162float(h)) : h;
    }
}

// ---------------------------------------------------------------------------
// Tensor-core GEMM via mma.sync m16n8k16 bf16 (fp32 acc), stacked-K hi/lo,
// now 2-stage DOUBLE-BUFFERED: prefetch chunk c+1 to regs before the MMA
// section of chunk c, store to alternate smem buffers after, ONE barrier
// per chunk. Fragments via explicit u32 LDS (proven R12 layout).
// CTA 128(m) x 128(n), 256 thr = 8 warps (wm x wn=4), warp tile 64x32.
// smem: 2 x As[128][40 bf16] + 2 x Bs[128][40 bf16] = 40960 B.
// ---------------------------------------------------------------------------
#define GMMA_SMEM (4 * 10240)   // 40960 B

__global__ __launch_bounds__(256, 2) void gemm_mma(
    const float* __restrict__ A, const __nv_bfloat16* __restrict__ Wt,
    const float* __restrict__ bias, float* __restrict__ C,
    int sT, int sB, int K, int Kcat, int Ntot)
{
    extern __shared__ char smb[];
    const int tid = threadIdx.x, lane = tid & 31, wid = tid >> 5;
    const int wm = wid & 1, wn = wid >> 1;
    const int grp = lane >> 2;          // 0..7
    const int qc  = lane & 3;           // 0..3
    const int mt = blockIdx.x << 7, nt = blockIdx.y << 7;

    float acc[4][4][4];
#pragma unroll
    for (int mi = 0; mi < 4; mi++)
#pragma unroll
        for (int ni = 0; ni < 4; ni++)
#pragma unroll
            for (int q = 0; q < 4; q++) acc[mi][ni][q] = 0.f;

    // loader coords
    const int r = tid >> 1, hf = tid & 1;       // A: row r, k-half hf
    const int bn = tid >> 1, s0 = tid & 1;      // B: row n, segment parity
    const int gm = mt + r;
    const int t0 = gm >> 9, b0 = gm & 511;
    const float* arow = A + (size_t)t0 * sT + (size_t)b0 * sB;
    const __nv_bfloat16* brow = Wt + (size_t)(nt + bn) * Kcat;

    const int nchunks = Kcat >> 5;

    unsigned oA[8];      // converted A chunk (16 bf16 packed)
    uint4 rB0, rB1;      // B chunk raw

    // ---- prefetch + convert chunk c into registers ----
    auto fetch = [&](int c) {
        int kbase = (c << 5) + (hf << 4);
        int lo = (kbase >= (K << 1));
        int ksrc = kbase; if (ksrc >= K) ksrc -= K; if (ksrc >= K) ksrc -= K;
        float4 v0 = *(const float4*)(arow + ksrc);
        float4 v1 = *(const float4*)(arow + ksrc + 4);
        float4 v2 = *(const float4*)(arow + ksrc + 8);
        float4 v3 = *(const float4*)(arow + ksrc + 12);
        float f[16] = {v0.x, v0.y, v0.z, v0.w, v1.x, v1.y, v1.z, v1.w,
                       v2.x, v2.y, v2.z, v2.w, v3.x, v3.y, v3.z, v3.w};
#pragma unroll
        for (int q = 0; q < 8; q++) {
            __nv_bfloat16 h0 = __float2bfloat16(f[2 * q]);
            __nv_bfloat16 h1 = __float2bfloat16(f[2 * q + 1]);
            if (lo) {
                h0 = __float2bfloat16(f[2 * q] - __bfloat162float(h0));
                h1 = __float2bfloat16(f[2 * q + 1] - __bfloat162float(h1));
            }
            oA[q] = (unsigned)__bfloat16_as_ushort(h0) |
                    ((unsigned)__bfloat16_as_ushort(h1) << 16);
        }
        const __nv_bfloat16* src = brow + (c << 5);
        rB0 = *(const uint4*)(src + (s0 << 3));
        rB1 = *(const uint4*)(src + ((s0 + 2) << 3));
    };
    // ---- store prefetched chunk into smem stage s ----
    auto stage_store = [&](int s) {
        char* Asb = smb + s * 10240;
        char* Bsb = smb + 20480 + s * 10240;
        uint4* dstA = (uint4*)(Asb + r * 80 + hf * 32);
        dstA[0] = make_uint4(oA[0], oA[1], oA[2], oA[3]);
        dstA[1] = make_uint4(oA[4], oA[5], oA[6], oA[7]);
        *(uint4*)(Bsb + bn * 80 + s0 * 16) = rB0;
        *(uint4*)(Bsb + bn * 80 + (s0 + 2) * 16) = rB1;
    };

    fetch(0);
    stage_store(0);
    __syncthreads();

    for (int c = 0; c < nchunks; c++) {
        if (c + 1 < nchunks) fetch(c + 1);   // gmem latency hides under MMAs

        const __nv_bfloat16* As = (const __nv_bfloat16*)(smb + (c & 1) * 10240);
        const __nv_bfloat16* Bs = (const __nv_bfloat16*)(smb + 20480 + (c & 1) * 10240);
#pragma unroll
        for (int ks = 0; ks < 2; ks++) {
            const int kofs = (ks << 4) + (qc << 1);
            uint32_t af[4][4];
#pragma unroll
            for (int mi = 0; mi < 4; mi++) {
                const __nv_bfloat16* ar0 = As + (wm * 64 + mi * 16 + grp) * 40 + kofs;
                af[mi][0] = *(const uint32_t*)(ar0);
                af[mi][1] = *(const uint32_t*)(ar0 + 8 * 40);
                af[mi][2] = *(const uint32_t*)(ar0 + 8);
                af[mi][3] = *(const uint32_t*)(ar0 + 8 * 40 + 8);
            }
            uint32_t bf[4][2];
#pragma unroll
            for (int ni = 0; ni < 4; ni++) {
                const __nv_bfloat16* br0 = Bs + (wn * 32 + ni * 8 + grp) * 40 + kofs;
                bf[ni][0] = *(const uint32_t*)(br0);
                bf[ni][1] = *(const uint32_t*)(br0 + 8);
            }
#pragma unroll
            for (int mi = 0; mi < 4; mi++)
#pragma unroll
                for (int ni = 0; ni < 4; ni++) {
                    asm volatile(
                        "mma.sync.aligned.m16n8k16.row.col.f32.bf16.bf16.f32 "
                        "{%0,%1,%2,%3}, {%4,%5,%6,%7}, {%8,%9}, {%0,%1,%2,%3};"
                        : "+f"(acc[mi][ni][0]), "+f"(acc[mi][ni][1]),
                          "+f"(acc[mi][ni][2]), "+f"(acc[mi][ni][3])
                        : "r"(af[mi][0]), "r"(af[mi][1]), "r"(af[mi][2]), "r"(af[mi][3]),
                          "r"(bf[ni][0]), "r"(bf[ni][1]));
                }
        }
        if (c + 1 < nchunks) stage_store((c + 1) & 1);
        __syncthreads();
    }

    // ---- epilogue: canonical C fragment ----
#pragma unroll
    for (int mi = 0; mi < 4; mi++) {
        int r0 = mt + wm * 64 + mi * 16 + grp;
#pragma unroll
        for (int ni = 0; ni < 4; ni++) {
            int col = nt + wn * 32 + ni * 8 + (qc << 1);
            float b0v = __ldg(bias + col), b1v = __ldg(bias + col + 1);
            *(float2*)(C + (size_t)r0 * Ntot + col) =
                make_float2(acc[mi][ni][0] + b0v, acc[mi][ni][1] + b1v);
            *(float2*)(C + (size_t)(r0 + 8) * Ntot + col) =
                make_float2(acc[mi][ni][2] + b0v, acc[mi][ni][3] + b1v);
        }
    }
}

// ---------------------------------------------------------------------------
// Layer-1 recurrence (proven R12/R4). 128 CTAs x 256 threads; CTA owns 4
// batch rows. thread = (j, ks in {0,1}); ks splits K=128. Per ks-half: 32 U
// rows in smem, 32 in registers. h as dup pairs {h,h} in smem.
// ---------------------------------------------------------------------------
#define REC1_SMEM ((64 * 512 + 2 * 128 * 8 + 128 * 20) * 4)  // 149504 B

__global__ __launch_bounds__(256, 1) void rec1_kernel()
{
    extern __shared__ float sm[];
    float* Us = sm;                  // [64][512]
    float* hd = sm + 64 * 512;       // [2][128][8]
    float* ex = hd + 2 * 128 * 8;    // [128][20]

    const int tid  = threadIdx.x;
    const int j    = tid & 127;
    const int ks   = tid >> 7;
    const int brow = blockIdx.x << 2;

    for (int i = tid; i < 64 * 128; i += 256) {
        int s = i >> 7;
        int c = (i & 127) << 2;
        int krow = (s < 32) ? s : (s + 32);
        *(float4*)(Us + s * 512 + c) = *(const float4*)(g_Up1 + krow * 512 + c);
    }
    const int rbase = ks * 64 + 32;
    ulonglong2 uw[32];
#pragma unroll
    for (int r = 0; r < 32; r++)
        uw[r] = *(const ulonglong2*)(g_Up1 + (rbase + r) * 512 + (j << 2));
    for (int i = tid; i < 2 * 128 * 8; i += 256) hd[i] = 0.f;
    float cc[4] = {0.f, 0.f, 0.f, 0.f};
    __syncthreads();

    const float* up0 = Us + (ks * 32) * 512 + (j << 2);
    int buf = 0;
    for (int t = 0; t < TT; t++) {
        u64 z2[4][2];
#pragma unroll
        for (int b = 0; b < 4; b++) { z2[b][0] = 0ull; z2[b][1] = 0ull; }

        ulonglong2 xv[4];
        if (ks == 0) {
#pragma unroll
            for (int b = 0; b < 4; b++)
                xv[b] = *(const ulonglong2*)(g_xw1 + ((size_t)(t * BB + brow + b) << 9) + (j << 2));
        }

        const float* hb = hd + buf * 1024;
        {
            const float* hp = hb + (ks * 64) * 8;
            const float* up = up0;
#pragma unroll 4
            for (int r = 0; r < 32; r++) {
                ulonglong2 hA = *(const ulonglong2*)(hp + (r << 3));
                ulonglong2 hB = *(const ulonglong2*)(hp + (r << 3) + 4);
                ulonglong2 uv = *(const ulonglong2*)(up);
                up += 512;
                fma2(z2[0][0], hA.x, uv.x); fma2(z2[0][1], hA.x, uv.y);
                fma2(z2[1][0], hA.y, uv.x); fma2(z2[1][1], hA.y, uv.y);
                fma2(z2[2][0], hB.x, uv.x); fma2(z2[2][1], hB.x, uv.y);
                fma2(z2[3][0], hB.y, uv.x); fma2(z2[3][1], hB.y, uv.y);
            }
        }
        {
            const float* hp = hb + rbase * 8;
#pragma unroll
            for (int r = 0; r < 32; r++) {
                ulonglong2 hA = *(const ulonglong2*)(hp + (r << 3));
                ulonglong2 hB = *(const ulonglong2*)(hp + (r << 3) + 4);
                fma2(z2[0][0], hA.x, uw[r].x); fma2(z2[0][1], hA.x, uw[r].y);
                fma2(z2[1][0], hA.y, uw[r].x); fma2(z2[1][1], hA.y, uw[r].y);
                fma2(z2[2][0], hB.x, uw[r].x); fma2(z2[2][1], hB.x, uw[r].y);
                fma2(z2[3][0], hB.y, uw[r].x); fma2(z2[3][1], hB.y, uw[r].y);
            }
        }
        if (ks) {
#pragma unroll
            for (int b = 0; b < 4; b++)
                *(ulonglong2*)(ex + j * 20 + (b << 2)) = make_ulonglong2(z2[b][0], z2[b][1]);
        }
        __syncthreads();
        if (ks == 0) {
            float* hn = hd + (buf ^ 1) * 1024;
            float hv[4];
#pragma unroll
            for (int b = 0; b < 4; b++) {
                ulonglong2 e = *(const ulonglong2*)(ex + j * 20 + (b << 2));
                add2(z2[b][0], e.x);
                add2(z2[b][1], e.y);
                add2(z2[b][0], xv[b].x);
                add2(z2[b][1], xv[b].y);
                float2 p0 = unpack2(z2[b][0]);
                float2 p1 = unpack2(z2[b][1]);
                float ig = sigf(p0.x);
                float fg = sigf(p0.y);
                float gg = fmaxf(p1.x, 0.f);
                float og = sigf(p1.y);
                cc[b] = fg * cc[b] + ig * gg;
                hv[b] = og * fmaxf(cc[b], 0.f);
                g_h1[((size_t)(t * BB + brow + b) << 7) + j] = hv[b];
            }
            *(ulonglong2*)(hn + (j << 3)) =
                make_ulonglong2(pack2(hv[0], hv[0]), pack2(hv[1], hv[1]));
            *(ulonglong2*)(hn + (j << 3) + 4) =
                make_ulonglong2(pack2(hv[2], hv[2]), pack2(hv[3], hv[3]));
        }
        __syncthreads();
        buf ^= 1;
    }
}

// ---------------------------------------------------------------------------
// Layer-2 recurrence (proven R12/R4), 4-way k-split. 128 CTAs x 256 threads.
// ---------------------------------------------------------------------------
#define REC2_SMEM ((32 * 256 + 2 * 64 * 8 + 3 * 64 * 20) * 4)  // 52480 B

__global__ __launch_bounds__(256, 1) void rec2_kernel()
{
    extern __shared__ float sm[];
    float* Us = sm;                  // [32][256]
    float* hd = sm + 32 * 256;       // [2][64][8]
    float* ex = hd + 2 * 64 * 8;     // [3][64][20]

    const int tid  = threadIdx.x;
    const int j    = tid & 63;
    const int ks   = tid >> 6;
    const int brow = blockIdx.x << 2;

    for (int i = tid; i < 32 * 64; i += 256) {
        int s = i >> 6;
        int c = (i & 63) << 2;
        int krow = ((s >> 3) << 4) + (s & 7);
        *(float4*)(Us + s * 256 + c) = *(const float4*)(g_Up2 + krow * 256 + c);
    }
    const int rbase = (ks << 4) + 8;
    ulonglong2 uw[8];
#pragma unroll
    for (int r = 0; r < 8; r++)
        uw[r] = *(const ulonglong2*)(g_Up2 + (rbase + r) * 256 + (j << 2));
    for (int i = tid; i < 2 * 64 * 8; i += 256) hd[i] = 0.f;
    float cc[4] = {0.f, 0.f, 0.f, 0.f};
    __syncthreads();

    const float* up0 = Us + (ks << 3) * 256 + (j << 2);
    int buf = 0;
    for (int t = 0; t < TT; t++) {
        u64 z2[4][2];
#pragma unroll
        for (int b = 0; b < 4; b++) { z2[b][0] = 0ull; z2[b][1] = 0ull; }

        ulonglong2 xv[4];
        if (ks == 0) {
#pragma unroll
            for (int b = 0; b < 4; b++)
                xv[b] = *(const ulonglong2*)(g_xw2 + ((size_t)(t * BB + brow + b) << 8) + (j << 2));
        }
        const float* hb = hd + buf * 512;
        {
            const float* hp = hb + (ks << 4) * 8;
            const float* up = up0;
#pragma unroll
            for (int r = 0; r < 8; r++) {
                ulonglong2 hA = *(const ulonglong2*)(hp + (r << 3));
                ulonglong2 hB = *(const ulonglong2*)(hp + (r << 3) + 4);
                ulonglong2 uv = *(const ulonglong2*)(up);
                up += 256;
                fma2(z2[0][0], hA.x, uv.x); fma2(z2[0][1], hA.x, uv.y);
                fma2(z2[1][0], hA.y, uv.x); fma2(z2[1][1], hA.y, uv.y);
                fma2(z2[2][0], hB.x, uv.x); fma2(z2[2][1], hB.x, uv.y);
                fma2(z2[3][0], hB.y, uv.x); fma2(z2[3][1], hB.y, uv.y);
            }
        }
        {
            const float* hp = hb + rbase * 8;
#pragma unroll
            for (int r = 0; r < 8; r++) {
                ulonglong2 hA = *(const ulonglong2*)(hp + (r << 3));
                ulonglong2 hB = *(const ulonglong2*)(hp + (r << 3) + 4);
                fma2(z2[0][0], hA.x, uw[r].x); fma2(z2[0][1], hA.x, uw[r].y);
                fma2(z2[1][0], hA.y, uw[r].x); fma2(z2[1][1], hA.y, uw[r].y);
                fma2(z2[2][0], hB.x, uw[r].x); fma2(z2[2][1], hB.x, uw[r].y);
                fma2(z2[3][0], hB.y, uw[r].x); fma2(z2[3][1], hB.y, uw[r].y);
            }
        }
        if (ks) {
            float* exq = ex + (ks - 1) * 1280 + j * 20;
#pragma unroll
            for (int b = 0; b < 4; b++)
                *(ulonglong2*)(exq + (b << 2)) = make_ulonglong2(z2[b][0], z2[b][1]);
        }
        __syncthreads();
        if (ks == 0) {
            float* hn = hd + (buf ^ 1) * 512;
            float hv[4];
#pragma unroll
            for (int b = 0; b < 4; b++) {
#pragma unroll
                for (int q = 0; q < 3; q++) {
                    ulonglong2 e = *(const ulonglong2*)(ex + q * 1280 + j * 20 + (b << 2));
                    add2(z2[b][0], e.x);
                    add2(z2[b][1], e.y);
                }
                add2(z2[b][0], xv[b].x);
                add2(z2[b][1], xv[b].y);
                float2 p0 = unpack2(z2[b][0]);
                float2 p1 = unpack2(z2[b][1]);
                float ig = sigf(p0.x);
                float fg = sigf(p0.y);
                float gg = fmaxf(p1.x, 0.f);
                float og = sigf(p1.y);
                cc[b] = fg * cc[b] + ig * gg;
                hv[b] = og * fmaxf(cc[b], 0.f);
                if (t == TT - 1)
                    g_h2[((brow + b) << 6) + j] = hv[b];
            }
            *(ulonglong2*)(hn + (j << 3)) =
                make_ulonglong2(pack2(hv[0], hv[0]), pack2(hv[1], hv[1]));
            *(ulonglong2*)(hn + (j << 3) + 4) =
                make_ulonglong2(pack2(hv[2], hv[2]), pack2(hv[3], hv[3]));
        }
        __syncthreads();
        buf ^= 1;
    }
}

// ---------------------------------------------------------------------------
// Dense head
// ---------------------------------------------------------------------------
__global__ void dense_kernel(const float* __restrict__ Wd1, const float* __restrict__ bd1,
                             const float* __restrict__ Wd2, const float* __restrict__ bd2,
                             float* __restrict__ out)
{
    int b = blockIdx.x * blockDim.x + threadIdx.x;
    if (b >= BB) return;
    float h[H2];
#pragma unroll
    for (int k = 0; k < H2; k++) h[k] = g_h2[(b << 6) + k];
    float acc = bd2[0];
    for (int d = 0; d < 25; d++) {
        float s = bd1[d];
#pragma unroll
        for (int k = 0; k < H2; k++) s += h[k] * Wd1[k * 25 + d];
        acc += s * Wd2[d];
    }
    out[b] = acc;
}

// ---------------------------------------------------------------------------
// Launch
// ---------------------------------------------------------------------------
extern "C" void kernel_launch(void* const* d_in, const int* in_sizes, int n_in,
                              void* d_out, int out_size)
{
    const float* x   = (const float*)d_in[0];
    const float* W1  = (const float*)d_in[1];
    const float* U1  = (const float*)d_in[2];
    const float* b1  = (const float*)d_in[3];
    const float* W2  = (const float*)d_in[4];
    const float* U2  = (const float*)d_in[5];
    const float* b2  = (const float*)d_in[6];
    const float* Wd1 = (const float*)d_in[7];
    const float* bd1 = (const float*)d_in[8];
    const float* Wd2 = (const float*)d_in[9];
    const float* bd2 = (const float*)d_in[10];
    float* out = (float*)d_out;

    cudaFuncSetAttribute(rec1_kernel, cudaFuncAttributeMaxDynamicSharedMemorySize, REC1_SMEM);
    cudaFuncSetAttribute(rec2_kernel, cudaFuncAttributeMaxDynamicSharedMemorySize, REC2_SMEM);

    float *pbp1, *pbp2, *pxw1, *pxw2, *ph1;
    void *pWt1, *pWt2;
    cudaGetSymbolAddress((void**)&pbp1, g_bp1);
    cudaGetSymbolAddress((void**)&pbp2, g_bp2);
    cudaGetSymbolAddress((void**)&pxw1, g_xw1);
    cudaGetSymbolAddress((void**)&pxw2, g_xw2);
    cudaGetSymbolAddress((void**)&ph1,  g_h1);
    cudaGetSymbolAddress(&pWt1, g_Wt1);
    cudaGetSymbolAddress(&pWt2, g_Wt2);

    // 1. weight permute + transposed stacked-K bf16 images
    prep_kernel<<<512, 256>>>(W1, U1, b1, W2, U2, b2);

    // 2. xW1 (tensor cores): x @ W1 -> g_xw1[t][b][:]   (Kcat = 192)
    gemm_mma<<<dim3((TT * BB) / 128, G1 / 128), 256, GMMA_SMEM>>>(
        x, (const __nv_bfloat16*)pWt1, pbp1, pxw1, FF, TT * FF, FF, 3 * FF, G1);

    // 3. layer-1 recurrence -> g_h1[t][b][:]
    rec1_kernel<<<BB / 4, 256, REC1_SMEM>>>();

    // 4. xW2 (tensor cores): h1 @ W2 -> g_xw2[t][b][:]  (Kcat = 384)
    gemm_mma<<<dim3((TT * BB) / 128, G2 / 128), 256, GMMA_SMEM>>>(
        ph1, (const __nv_bfloat16*)pWt2, pbp2, pxw2, BB * H1, H1, H1, 3 * H1, G2);

    // 5. layer-2 recurrence -> g_h2[b][:]
    rec2_kernel<<<BB / 4, 256, REC2_SMEM>>>();

    // 6. dense head
    dense_kernel<<<2, 256>>>(Wd1, bd1, Wd2, bd2, out);
}

// round 16
// speedup vs baseline: 1.0910x; 1.0299x over previous
#include <cuda_runtime.h>
#include <cuda_bf16.h>
#include <cstddef>
#include <cstdint>

// Problem constants
#define BB 512   // batch
#define TT 512   // timesteps
#define FF 64    // input features
#define H1 128   // layer1 hidden
#define G1 512   // 4*H1
#define H2 64    // layer2 hidden
#define G2 256   // 4*H2

typedef unsigned long long u64;

// ---------------------------------------------------------------------------
// Packed fp32x2 helpers
// ---------------------------------------------------------------------------
__device__ __forceinline__ u64 pack2(float lo, float hi) {
    u64 r; asm("mov.b64 %0, {%1, %2};" : "=l"(r) : "f"(lo), "f"(hi)); return r;
}
__device__ __forceinline__ float2 unpack2(u64 v) {
    float2 f; asm("mov.b64 {%0, %1}, %2;" : "=f"(f.x), "=f"(f.y) : "l"(v)); return f;
}
__device__ __forceinline__ void fma2(u64& d, u64 a, u64 b) {
    asm("fma.rn.f32x2 %0, %1, %2, %0;" : "+l"(d) : "l"(a), "l"(b));
}
__device__ __forceinline__ void add2(u64& d, u64 a) {
    asm("add.rn.f32x2 %0, %0, %1;" : "+l"(d) : "l"(a));
}

// ---------------------------------------------------------------------------
// Device scratch
// ---------------------------------------------------------------------------
__device__ float g_bp1[G1];
__device__ float g_Up1[H1 * G1];        // U1 permuted: [k][j*4+gate]
__device__ float g_bp2[G2];
__device__ float g_Up2[H2 * G2];
// Transposed stacked-K weights: [n][k'] with k' = [Wh | Wl | Wh] (3rd unused now)
__device__ __align__(16) __nv_bfloat16 g_Wt1[G1 * 3 * FF];   // [512][192]
__device__ __align__(16) __nv_bfloat16 g_Wt2[G2 * 3 * H1];   // [256][384]
__device__ float g_xw1[(size_t)TT * BB * G1];  // [t][b][j*4+gate]
__device__ float g_h1[(size_t)TT * BB * H1];   // [t][b][j]
__device__ float g_xw2[(size_t)TT * BB * G2];  // [t][b][j*4+gate]
__device__ float g_h2[BB * H2];                // final layer2 h

__device__ __forceinline__ float sigf(float x) {
    return __fdividef(1.0f, 1.0f + __expf(-x));
}

// ---------------------------------------------------------------------------
// Prep: permuted fp32 bias/U (n = j*4+gate, gate order i,f,g,o) + transposed
// stacked-K bf16 weights Wt[n][k'] with k' spans [Wh | Wl | Wh].
// ---------------------------------------------------------------------------
__global__ void prep_kernel(const float* __restrict__ W1, const float* __restrict__ U1,
                            const float* __restrict__ b1, const float* __restrict__ W2,
                            const float* __restrict__ U2, const float* __restrict__ b2)
{
    int i = blockIdx.x * blockDim.x + threadIdx.x;
    if (i < G1) {
        int j = i >> 2, gi = i & 3;
        g_bp1[i] = b1[gi * H1 + j];
    }
    if (i < H1 * G1) {
        int k = i >> 9, n = i & 511;
        int j = n >> 2, gi = n & 3;
        g_Up1[i] = U1[k * G1 + gi * H1 + j];
    }
    if (i < G2) {
        int j = i >> 2, gi = i & 3;
        g_bp2[i] = b2[gi * H2 + j];
    }
    if (i < H2 * G2) {
        int k = i >> 8, n = i & 255;
        int j = n >> 2, gi = n & 3;
        g_Up2[i] = U2[k * G2 + gi * H2 + j];
    }
    if (i < G1 * 3 * FF) {   // Wt1[n][kp], n in [0,512), kp in [0,192)
        int n = i / 192, kp = i - n * 192;
        int p = kp / FF, ks = kp - p * FF;
        float v = W1[ks * G1 + (n & 3) * H1 + (n >> 2)];
        __nv_bfloat16 h = __float2bfloat16(v);
        g_Wt1[i] = (p == 1) ? __float2bfloat16(v - __bfloat162float(h)) : h;
    }
    if (i < G2 * 3 * H1) {   // Wt2[n][kp], n in [0,256), kp in [0,384)
        int n = i / 384, kp = i - n * 384;
        int p = kp / H1, ks = kp - p * H1;
        float v = W2[ks * G2 + (n & 3) * H2 + (n >> 2)];
        __nv_bfloat16 h = __float2bfloat16(v);
        g_Wt2[i] = (p == 1) ? __float2bfloat16(v - __bfloat162float(h)) : h;
    }
}

// ---------------------------------------------------------------------------
// Tensor-core GEMM, 3-pass fp32-via-bf16 with FRAGMENT REUSE.
// Per base-K chunk of 32: smem holds Ah, Al, Bh, Bl (each [128][40]bf16).
// acc += Ah*Bh + Al*Bh + Ah*Bl  (AlBl dropped, ~2^-16 rel).
// Fragments loaded once per pass-group: 48 LDS per warp per chunk (was 144).
// CTA 128(m) x 128(n), 256 thr = 8 warps, warp tile 64x32. Fragment index
// arithmetic identical to proven R12 kernel.
// ---------------------------------------------------------------------------
#define GMMA_SMEM (4 * 10240)   // Ah, Al, Bh, Bl = 40960 B

__global__ __launch_bounds__(256, 2) void gemm_mma(
    const float* __restrict__ A, const __nv_bfloat16* __restrict__ Wt,
    const float* __restrict__ bias, float* __restrict__ C,
    int sT, int sB, int K, int Kcat, int Ntot)
{
    extern __shared__ char smb[];
    __nv_bfloat16* Ash = (__nv_bfloat16*)(smb);             // [128][40]
    __nv_bfloat16* Asl = (__nv_bfloat16*)(smb + 10240);
    __nv_bfloat16* Bsh = (__nv_bfloat16*)(smb + 20480);
    __nv_bfloat16* Bsl = (__nv_bfloat16*)(smb + 30720);
    const int tid = threadIdx.x, lane = tid & 31, wid = tid >> 5;
    const int wm = wid & 1, wn = wid >> 1;
    const int grp = lane >> 2;          // 0..7
    const int qc  = lane & 3;           // 0..3
    const int mt = blockIdx.x << 7, nt = blockIdx.y << 7;

    float acc[4][4][4];
#pragma unroll
    for (int mi = 0; mi < 4; mi++)
#pragma unroll
        for (int ni = 0; ni < 4; ni++)
#pragma unroll
            for (int q = 0; q < 4; q++) acc[mi][ni][q] = 0.f;

    // loader coords
    const int r = tid >> 1, hf = tid & 1;       // A: row r, k-half hf
    const int bn = tid >> 1, s0 = tid & 1;      // B: row n, segment parity
    const int gm = mt + r;
    const int t0 = gm >> 9, b0 = gm & 511;
    const float* arow = A + (size_t)t0 * sT + (size_t)b0 * sB;
    const __nv_bfloat16* brow = Wt + (size_t)(nt + bn) * Kcat;

    const int nchunks = K >> 5;
    for (int c = 0; c < nchunks; c++) {
        {   // ---- A: 16 fp32 -> bf16 hi AND lo ----
            int ksrc = (c << 5) + (hf << 4);
            float4 v0 = *(const float4*)(arow + ksrc);
            float4 v1 = *(const float4*)(arow + ksrc + 4);
            float4 v2 = *(const float4*)(arow + ksrc + 8);
            float4 v3 = *(const float4*)(arow + ksrc + 12);
            float f[16] = {v0.x, v0.y, v0.z, v0.w, v1.x, v1.y, v1.z, v1.w,
                           v2.x, v2.y, v2.z, v2.w, v3.x, v3.y, v3.z, v3.w};
            unsigned oh[8], ol[8];
#pragma unroll
            for (int q = 0; q < 8; q++) {
                __nv_bfloat16 h0 = __float2bfloat16(f[2 * q]);
                __nv_bfloat16 h1 = __float2bfloat16(f[2 * q + 1]);
                __nv_bfloat16 l0 = __float2bfloat16(f[2 * q] - __bfloat162float(h0));
                __nv_bfloat16 l1 = __float2bfloat16(f[2 * q + 1] - __bfloat162float(h1));
                oh[q] = (unsigned)__bfloat16_as_ushort(h0) |
                        ((unsigned)__bfloat16_as_ushort(h1) << 16);
                ol[q] = (unsigned)__bfloat16_as_ushort(l0) |
                        ((unsigned)__bfloat16_as_ushort(l1) << 16);
            }
            uint4* dh = (uint4*)((char*)Ash + r * 80 + hf * 32);
            dh[0] = make_uint4(oh[0], oh[1], oh[2], oh[3]);
            dh[1] = make_uint4(oh[4], oh[5], oh[6], oh[7]);
            uint4* dl = (uint4*)((char*)Asl + r * 80 + hf * 32);
            dl[0] = make_uint4(ol[0], ol[1], ol[2], ol[3]);
            dl[1] = make_uint4(ol[4], ol[5], ol[6], ol[7]);
        }
        {   // ---- B: Wh rows at k'=c*32, Wl rows at k'=K+c*32 ----
            const __nv_bfloat16* sh = brow + (c << 5);
            const __nv_bfloat16* sl = brow + K + (c << 5);
#pragma unroll
            for (int s = 0; s < 2; s++) {
                int seg = s0 + (s << 1);   // 0..3
                *(uint4*)((char*)Bsh + bn * 80 + seg * 16) = *(const uint4*)(sh + (seg << 3));
                *(uint4*)((char*)Bsl + bn * 80 + seg * 16) = *(const uint4*)(sl + (seg << 3));
            }
        }
        __syncthreads();
#pragma unroll
        for (int ks = 0; ks < 2; ks++) {
            const int kofs = (ks << 4) + (qc << 1);
            // Ah fragments (live through all 3 passes)
            uint32_t afh[4][4];
#pragma unroll
            for (int mi = 0; mi < 4; mi++) {
                const __nv_bfloat16* ar0 = Ash + (wm * 64 + mi * 16 + grp) * 40 + kofs;
                afh[mi][0] = *(const uint32_t*)(ar0);
                afh[mi][1] = *(const uint32_t*)(ar0 + 8 * 40);
                afh[mi][2] = *(const uint32_t*)(ar0 + 8);
                afh[mi][3] = *(const uint32_t*)(ar0 + 8 * 40 + 8);
            }
            // Bh fragments (passes 1-2)
            uint32_t bfh[4][2];
#pragma unroll
            for (int ni = 0; ni < 4; ni++) {
                const __nv_bfloat16* br0 = Bsh + (wn * 32 + ni * 8 + grp) * 40 + kofs;
                bfh[ni][0] = *(const uint32_t*)(br0);
                bfh[ni][1] = *(const uint32_t*)(br0 + 8);
            }
            // pass 1: Ah * Bh
#pragma unroll
            for (int mi = 0; mi < 4; mi++)
#pragma unroll
                for (int ni = 0; ni < 4; ni++)
                    asm volatile(
                        "mma.sync.aligned.m16n8k16.row.col.f32.bf16.bf16.f32 "
                        "{%0,%1,%2,%3}, {%4,%5,%6,%7}, {%8,%9}, {%0,%1,%2,%3};"
                        : "+f"(acc[mi][ni][0]), "+f"(acc[mi][ni][1]),
                          "+f"(acc[mi][ni][2]), "+f"(acc[mi][ni][3])
                        : "r"(afh[mi][0]), "r"(afh[mi][1]), "r"(afh[mi][2]), "r"(afh[mi][3]),
                          "r"(bfh[ni][0]), "r"(bfh[ni][1]));
            // pass 2: Al * Bh (Al fragments replace nothing; Bh reused)
            {
                uint32_t afl[4][4];
#pragma unroll
                for (int mi = 0; mi < 4; mi++) {
                    const __nv_bfloat16* ar0 = Asl + (wm * 64 + mi * 16 + grp) * 40 + kofs;
                    afl[mi][0] = *(const uint32_t*)(ar0);
                    afl[mi][1] = *(const uint32_t*)(ar0 + 8 * 40);
                    afl[mi][2] = *(const uint32_t*)(ar0 + 8);
                    afl[mi][3] = *(const uint32_t*)(ar0 + 8 * 40 + 8);
                }
#pragma unroll
                for (int mi = 0; mi < 4; mi++)
#pragma unroll
                    for (int ni = 0; ni < 4; ni++)
                        asm volatile(
                            "mma.sync.aligned.m16n8k16.row.col.f32.bf16.bf16.f32 "
                            "{%0,%1,%2,%3}, {%4,%5,%6,%7}, {%8,%9}, {%0,%1,%2,%3};"
                            : "+f"(acc[mi][ni][0]), "+f"(acc[mi][ni][1]),
                              "+f"(acc[mi][ni][2]), "+f"(acc[mi][ni][3])
                            : "r"(afl[mi][0]), "r"(afl[mi][1]), "r"(afl[mi][2]), "r"(afl[mi][3]),
                              "r"(bfh[ni][0]), "r"(bfh[ni][1]));
            }
            // pass 3: Ah * Bl (Ah reused; Bl fragments)
            {
                uint32_t bfl[4][2];
#pragma unroll
                for (int ni = 0; ni < 4; ni++) {
                    const __nv_bfloat16* br0 = Bsl + (wn * 32 + ni * 8 + grp) * 40 + kofs;
                    bfl[ni][0] = *(const uint32_t*)(br0);
                    bfl[ni][1] = *(const uint32_t*)(br0 + 8);
                }
#pragma unroll
                for (int mi = 0; mi < 4; mi++)
#pragma unroll
                    for (int ni = 0; ni < 4; ni++)
                        asm volatile(
                            "mma.sync.aligned.m16n8k16.row.col.f32.bf16.bf16.f32 "
                            "{%0,%1,%2,%3}, {%4,%5,%6,%7}, {%8,%9}, {%0,%1,%2,%3};"
                            : "+f"(acc[mi][ni][0]), "+f"(acc[mi][ni][1]),
                              "+f"(acc[mi][ni][2]), "+f"(acc[mi][ni][3])
                            : "r"(afh[mi][0]), "r"(afh[mi][1]), "r"(afh[mi][2]), "r"(afh[mi][3]),
                              "r"(bfl[ni][0]), "r"(bfl[ni][1]));
            }
        }
        __syncthreads();
    }

    // ---- epilogue: canonical C fragment ----
#pragma unroll
    for (int mi = 0; mi < 4; mi++) {
        int r0 = mt + wm * 64 + mi * 16 + grp;
#pragma unroll
        for (int ni = 0; ni < 4; ni++) {
            int col = nt + wn * 32 + ni * 8 + (qc << 1);
            float b0v = __ldg(bias + col), b1v = __ldg(bias + col + 1);
            *(float2*)(C + (size_t)r0 * Ntot + col) =
                make_float2(acc[mi][ni][0] + b0v, acc[mi][ni][1] + b1v);
            *(float2*)(C + (size_t)(r0 + 8) * Ntot + col) =
                make_float2(acc[mi][ni][2] + b0v, acc[mi][ni][3] + b1v);
        }
    }
}

// ---------------------------------------------------------------------------
// Layer-1 recurrence, 4-way k-split. 128 CTAs x 512 threads.
// thread = (j in [0,128), q in [0,4)); q owns k-rows [q*32, q*32+32):
// 20 rows from smem, 12 from registers. Quarters 1..3 write partials to ex;
// quarter 0 (warps 0-3, one per SMSP) combines + gates (R12-proven tail).
// h as dup pairs {h,h} in smem (broadcast reads).
// ---------------------------------------------------------------------------
#define REC1_SMEM ((80 * 512 + 2 * 128 * 8 + 3 * 128 * 20) * 4)  // 202752 B

__global__ __launch_bounds__(512, 1) void rec1_kernel()
{
    extern __shared__ float sm[];
    float* Us = sm;                  // [80][512]: s = q*20 + r <-> krow = q*32 + r
    float* hd = sm + 80 * 512;       // [2][128][8]
    float* ex = hd + 2 * 128 * 8;    // [3][128][20]

    const int tid  = threadIdx.x;
    const int j    = tid & 127;
    const int q    = tid >> 7;       // 0..3
    const int brow = blockIdx.x << 2;

    // smem U rows: 20 per quarter
    for (int i = tid; i < 80 * 128; i += 512) {
        int s = i >> 7;
        int c = (i & 127) << 2;
        int krow = (s / 20) * 32 + (s % 20);
        *(float4*)(Us + s * 512 + c) = *(const float4*)(g_Up1 + krow * 512 + c);
    }
    // reg U rows: krow = q*32 + 20 + r, r < 12
    const int rbase = (q << 5) + 20;
    ulonglong2 uw[12];
#pragma unroll
    for (int r = 0; r < 12; r++)
        uw[r] = *(const ulonglong2*)(g_Up1 + (rbase + r) * 512 + (j << 2));
    for (int i = tid; i < 2 * 128 * 8; i += 512) hd[i] = 0.f;
    float cc[4] = {0.f, 0.f, 0.f, 0.f};
    __syncthreads();

    const float* up0 = Us + (q * 20) * 512 + (j << 2);
    int buf = 0;
    for (int t = 0; t < TT; t++) {
        u64 z2[4][2];
#pragma unroll
        for (int b = 0; b < 4; b++) { z2[b][0] = 0ull; z2[b][1] = 0ull; }

        ulonglong2 xv[4];
        if (q == 0) {
#pragma unroll
            for (int b = 0; b < 4; b++)
                xv[b] = *(const ulonglong2*)(g_xw1 + ((size_t)(t * BB + brow + b) << 9) + (j << 2));
        }

        const float* hb = hd + buf * 1024;
        {   // smem rows: krow = q*32 + [0,20)
            const float* hp = hb + (q << 5) * 8;
            const float* up = up0;
#pragma unroll 4
            for (int r = 0; r < 20; r++) {
                ulonglong2 hA = *(const ulonglong2*)(hp + (r << 3));
                ulonglong2 hB = *(const ulonglong2*)(hp + (r << 3) + 4);
                ulonglong2 uv = *(const ulonglong2*)(up);
                up += 512;
                fma2(z2[0][0], hA.x, uv.x); fma2(z2[0][1], hA.x, uv.y);
                fma2(z2[1][0], hA.y, uv.x); fma2(z2[1][1], hA.y, uv.y);
                fma2(z2[2][0], hB.x, uv.x); fma2(z2[2][1], hB.x, uv.y);
                fma2(z2[3][0], hB.y, uv.x); fma2(z2[3][1], hB.y, uv.y);
            }
        }
        {   // reg rows: krow = q*32 + [20,32)
            const float* hp = hb + rbase * 8;
#pragma unroll
            for (int r = 0; r < 12; r++) {
                ulonglong2 hA = *(const ulonglong2*)(hp + (r << 3));
                ulonglong2 hB = *(const ulonglong2*)(hp + (r << 3) + 4);
                fma2(z2[0][0], hA.x, uw[r].x); fma2(z2[0][1], hA.x, uw[r].y);
                fma2(z2[1][0], hA.y, uw[r].x); fma2(z2[1][1], hA.y, uw[r].y);
                fma2(z2[2][0], hB.x, uw[r].x); fma2(z2[2][1], hB.x, uw[r].y);
                fma2(z2[3][0], hB.y, uw[r].x); fma2(z2[3][1], hB.y, uw[r].y);
            }
        }
        if (q) {
            float* exq = ex + (q - 1) * 2560 + j * 20;
#pragma unroll
            for (int b = 0; b < 4; b++)
                *(ulonglong2*)(exq + (b << 2)) = make_ulonglong2(z2[b][0], z2[b][1]);
        }
        __syncthreads();
        if (q == 0) {
            float* hn = hd + (buf ^ 1) * 1024;
            float hv[4];
#pragma unroll
            for (int b = 0; b < 4; b++) {
#pragma unroll
                for (int p = 0; p < 3; p++) {
                    ulonglong2 e = *(const ulonglong2*)(ex + p * 2560 + j * 20 + (b << 2));
                    add2(z2[b][0], e.x);
                    add2(z2[b][1], e.y);
                }
                add2(z2[b][0], xv[b].x);
                add2(z2[b][1], xv[b].y);
                float2 p0 = unpack2(z2[b][0]);
                float2 p1 = unpack2(z2[b][1]);
                float ig = sigf(p0.x);
                float fg = sigf(p0.y);
                float gg = fmaxf(p1.x, 0.f);
                float og = sigf(p1.y);
                cc[b] = fg * cc[b] + ig * gg;
                hv[b] = og * fmaxf(cc[b], 0.f);
                g_h1[((size_t)(t * BB + brow + b) << 7) + j] = hv[b];
            }
            *(ulonglong2*)(hn + (j << 3)) =
                make_ulonglong2(pack2(hv[0], hv[0]), pack2(hv[1], hv[1]));
            *(ulonglong2*)(hn + (j << 3) + 4) =
                make_ulonglong2(pack2(hv[2], hv[2]), pack2(hv[3], hv[3]));
        }
        __syncthreads();
        buf ^= 1;
    }
}

// ---------------------------------------------------------------------------
// Layer-2 recurrence (proven R12/R4), 4-way k-split. 128 CTAs x 256 threads.
// ---------------------------------------------------------------------------
#define REC2_SMEM ((32 * 256 + 2 * 64 * 8 + 3 * 64 * 20) * 4)  // 52480 B

__global__ __launch_bounds__(256, 1) void rec2_kernel()
{
    extern __shared__ float sm[];
    float* Us = sm;                  // [32][256]
    float* hd = sm + 32 * 256;       // [2][64][8]
    float* ex = hd + 2 * 64 * 8;     // [3][64][20]

    const int tid  = threadIdx.x;
    const int j    = tid & 63;
    const int ks   = tid >> 6;
    const int brow = blockIdx.x << 2;

    for (int i = tid; i < 32 * 64; i += 256) {
        int s = i >> 6;
        int c = (i & 63) << 2;
        int krow = ((s >> 3) << 4) + (s & 7);
        *(float4*)(Us + s * 256 + c) = *(const float4*)(g_Up2 + krow * 256 + c);
    }
    const int rbase = (ks << 4) + 8;
    ulonglong2 uw[8];
#pragma unroll
    for (int r = 0; r < 8; r++)
        uw[r] = *(const ulonglong2*)(g_Up2 + (rbase + r) * 256 + (j << 2));
    for (int i = tid; i < 2 * 64 * 8; i += 256) hd[i] = 0.f;
    float cc[4] = {0.f, 0.f, 0.f, 0.f};
    __syncthreads();

    const float* up0 = Us + (ks << 3) * 256 + (j << 2);
    int buf = 0;
    for (int t = 0; t < TT; t++) {
        u64 z2[4][2];
#pragma unroll
        for (int b = 0; b < 4; b++) { z2[b][0] = 0ull; z2[b][1] = 0ull; }

        ulonglong2 xv[4];
        if (ks == 0) {
#pragma unroll
            for (int b = 0; b < 4; b++)
                xv[b] = *(const ulonglong2*)(g_xw2 + ((size_t)(t * BB + brow + b) << 8) + (j << 2));
        }
        const float* hb = hd + buf * 512;
        {
            const float* hp = hb + (ks << 4) * 8;
            const float* up = up0;
#pragma unroll
            for (int r = 0; r < 8; r++) {
                ulonglong2 hA = *(const ulonglong2*)(hp + (r << 3));
                ulonglong2 hB = *(const ulonglong2*)(hp + (r << 3) + 4);
                ulonglong2 uv = *(const ulonglong2*)(up);
                up += 256;
                fma2(z2[0][0], hA.x, uv.x); fma2(z2[0][1], hA.x, uv.y);
                fma2(z2[1][0], hA.y, uv.x); fma2(z2[1][1], hA.y, uv.y);
                fma2(z2[2][0], hB.x, uv.x); fma2(z2[2][1], hB.x, uv.y);
                fma2(z2[3][0], hB.y, uv.x); fma2(z2[3][1], hB.y, uv.y);
            }
        }
        {
            const float* hp = hb + rbase * 8;
#pragma unroll
            for (int r = 0; r < 8; r++) {
                ulonglong2 hA = *(const ulonglong2*)(hp + (r << 3));
                ulonglong2 hB = *(const ulonglong2*)(hp + (r << 3) + 4);
                fma2(z2[0][0], hA.x, uw[r].x); fma2(z2[0][1], hA.x, uw[r].y);
                fma2(z2[1][0], hA.y, uw[r].x); fma2(z2[1][1], hA.y, uw[r].y);
                fma2(z2[2][0], hB.x, uw[r].x); fma2(z2[2][1], hB.x, uw[r].y);
                fma2(z2[3][0], hB.y, uw[r].x); fma2(z2[3][1], hB.y, uw[r].y);
            }
        }
        if (ks) {
            float* exq = ex + (ks - 1) * 1280 + j * 20;
#pragma unroll
            for (int b = 0; b < 4; b++)
                *(ulonglong2*)(exq + (b << 2)) = make_ulonglong2(z2[b][0], z2[b][1]);
        }
        __syncthreads();
        if (ks == 0) {
            float* hn = hd + (buf ^ 1) * 512;
            float hv[4];
#pragma unroll
            for (int b = 0; b < 4; b++) {
#pragma unroll
                for (int p = 0; p < 3; p++) {
                    ulonglong2 e = *(const ulonglong2*)(ex + p * 1280 + j * 20 + (b << 2));
                    add2(z2[b][0], e.x);
                    add2(z2[b][1], e.y);
                }
                add2(z2[b][0], xv[b].x);
                add2(z2[b][1], xv[b].y);
                float2 p0 = unpack2(z2[b][0]);
                float2 p1 = unpack2(z2[b][1]);
                float ig = sigf(p0.x);
                float fg = sigf(p0.y);
                float gg = fmaxf(p1.x, 0.f);
                float og = sigf(p1.y);
                cc[b] = fg * cc[b] + ig * gg;
                hv[b] = og * fmaxf(cc[b], 0.f);
                if (t == TT - 1)
                    g_h2[((brow + b) << 6) + j] = hv[b];
            }
            *(ulonglong2*)(hn + (j << 3)) =
                make_ulonglong2(pack2(hv[0], hv[0]), pack2(hv[1], hv[1]));
            *(ulonglong2*)(hn + (j << 3) + 4) =
                make_ulonglong2(pack2(hv[2], hv[2]), pack2(hv[3], hv[3]));
        }
        __syncthreads();
        buf ^= 1;
    }
}

// ---------------------------------------------------------------------------
// Dense head
// ---------------------------------------------------------------------------
__global__ void dense_kernel(const float* __restrict__ Wd1, const float* __restrict__ bd1,
                             const float* __restrict__ Wd2, const float* __restrict__ bd2,
                             float* __restrict__ out)
{
    int b = blockIdx.x * blockDim.x + threadIdx.x;
    if (b >= BB) return;
    float h[H2];
#pragma unroll
    for (int k = 0; k < H2; k++) h[k] = g_h2[(b << 6) + k];
    float acc = bd2[0];
    for (int d = 0; d < 25; d++) {
        float s = bd1[d];
#pragma unroll
        for (int k = 0; k < H2; k++) s += h[k] * Wd1[k * 25 + d];
        acc += s * Wd2[d];
    }
    out[b] = acc;
}

// ---------------------------------------------------------------------------
// Launch
// ---------------------------------------------------------------------------
extern "C" void kernel_launch(void* const* d_in, const int* in_sizes, int n_in,
                              void* d_out, int out_size)
{
    const float* x   = (const float*)d_in[0];
    const float* W1  = (const float*)d_in[1];
    const float* U1  = (const float*)d_in[2];
    const float* b1  = (const float*)d_in[3];
    const float* W2  = (const float*)d_in[4];
    const float* U2  = (const float*)d_in[5];
    const float* b2  = (const float*)d_in[6];
    const float* Wd1 = (const float*)d_in[7];
    const float* bd1 = (const float*)d_in[8];
    const float* Wd2 = (const float*)d_in[9];
    const float* bd2 = (const float*)d_in[10];
    float* out = (float*)d_out;

    cudaFuncSetAttribute(rec1_kernel, cudaFuncAttributeMaxDynamicSharedMemorySize, REC1_SMEM);
    cudaFuncSetAttribute(rec2_kernel, cudaFuncAttributeMaxDynamicSharedMemorySize, REC2_SMEM);

    float *pbp1, *pbp2, *pxw1, *pxw2, *ph1;
    void *pWt1, *pWt2;
    cudaGetSymbolAddress((void**)&pbp1, g_bp1);
    cudaGetSymbolAddress((void**)&pbp2, g_bp2);
    cudaGetSymbolAddress((void**)&pxw1, g_xw1);
    cudaGetSymbolAddress((void**)&pxw2, g_xw2);
    cudaGetSymbolAddress((void**)&ph1,  g_h1);
    cudaGetSymbolAddress(&pWt1, g_Wt1);
    cudaGetSymbolAddress(&pWt2, g_Wt2);

    // 1. weight permute + transposed stacked-K bf16 images
    prep_kernel<<<512, 256>>>(W1, U1, b1, W2, U2, b2);

    // 2. xW1 (tensor cores, 3-pass): x @ W1 -> g_xw1[t][b][:]
    gemm_mma<<<dim3((TT * BB) / 128, G1 / 128), 256, GMMA_SMEM>>>(
        x, (const __nv_bfloat16*)pWt1, pbp1, pxw1, FF, TT * FF, FF, 3 * FF, G1);

    // 3. layer-1 recurrence (4-way k-split) -> g_h1[t][b][:]
    rec1_kernel<<<BB / 4, 512, REC1_SMEM>>>();

    // 4. xW2 (tensor cores, 3-pass): h1 @ W2 -> g_xw2[t][b][:]
    gemm_mma<<<dim3((TT * BB) / 128, G2 / 128), 256, GMMA_SMEM>>>(
        ph1, (const __nv_bfloat16*)pWt2, pbp2, pxw2, BB * H1, H1, H1, 3 * H1, G2);

    // 5. layer-2 recurrence -> g_h2[b][:]
    rec2_kernel<<<BB / 4, 256, REC2_SMEM>>>();

    // 6. dense head
    dense_kernel<<<2, 256>>>(Wd1, bd1, Wd2, bd2, out);
}

// round 17
// speedup vs baseline: 1.1053x; 1.0131x over previous
#include <cuda_runtime.h>
#include <cuda_bf16.h>
#include <cstddef>
#include <cstdint>

// Problem constants
#define BB 512   // batch
#define TT 512   // timesteps
#define FF 64    // input features
#define H1 128   // layer1 hidden
#define G1 512   // 4*H1
#define H2 64    // layer2 hidden
#define G2 256   // 4*H2

typedef unsigned long long u64;

// ---------------------------------------------------------------------------
// Packed fp32x2 helpers
// ---------------------------------------------------------------------------
__device__ __forceinline__ u64 pack2(float lo, float hi) {
    u64 r; asm("mov.b64 %0, {%1, %2};" : "=l"(r) : "f"(lo), "f"(hi)); return r;
}
__device__ __forceinline__ float2 unpack2(u64 v) {
    float2 f; asm("mov.b64 {%0, %1}, %2;" : "=f"(f.x), "=f"(f.y) : "l"(v)); return f;
}
__device__ __forceinline__ void fma2(u64& d, u64 a, u64 b) {
    asm("fma.rn.f32x2 %0, %1, %2, %0;" : "+l"(d) : "l"(a), "l"(b));
}
__device__ __forceinline__ void add2(u64& d, u64 a) {
    asm("add.rn.f32x2 %0, %0, %1;" : "+l"(d) : "l"(a));
}

// ---------------------------------------------------------------------------
// Device scratch
// ---------------------------------------------------------------------------
__device__ float g_bp1[G1];
__device__ float g_Up1[H1 * G1];        // U1 permuted: [k][j*4+gate]
__device__ float g_bp2[G2];
__device__ float g_Up2[H2 * G2];
// Transposed stacked-K weights: [n][k'] with k' = [Wh | Wl | Wh]
__device__ __align__(16) __nv_bfloat16 g_Wt1[G1 * 3 * FF];   // [512][192]
__device__ __align__(16) __nv_bfloat16 g_Wt2[G2 * 3 * H1];   // [256][384]
__device__ float g_xw1[(size_t)TT * BB * G1];  // [t][b][j*4+gate]
__device__ float g_h1[(size_t)TT * BB * H1];   // [t][b][j]
__device__ float g_xw2[(size_t)TT * BB * G2];  // [t][b][j*4+gate]
__device__ float g_h2[BB * H2];                // final layer2 h

__device__ __forceinline__ float sigf(float x) {
    return __fdividef(1.0f, 1.0f + __expf(-x));
}

// ---------------------------------------------------------------------------
// Prep: permuted fp32 bias/U (n = j*4+gate, gate order i,f,g,o) + transposed
// stacked-K bf16 weights Wt[n][k'] with k' spans [Wh | Wl | Wh].
// ---------------------------------------------------------------------------
__global__ void prep_kernel(const float* __restrict__ W1, const float* __restrict__ U1,
                            const float* __restrict__ b1, const float* __restrict__ W2,
                            const float* __restrict__ U2, const float* __restrict__ b2)
{
    int i = blockIdx.x * blockDim.x + threadIdx.x;
    if (i < G1) {
        int j = i >> 2, gi = i & 3;
        g_bp1[i] = b1[gi * H1 + j];
    }
    if (i < H1 * G1) {
        int k = i >> 9, n = i & 511;
        int j = n >> 2, gi = n & 3;
        g_Up1[i] = U1[k * G1 + gi * H1 + j];
    }
    if (i < G2) {
        int j = i >> 2, gi = i & 3;
        g_bp2[i] = b2[gi * H2 + j];
    }
    if (i < H2 * G2) {
        int k = i >> 8, n = i & 255;
        int j = n >> 2, gi = n & 3;
        g_Up2[i] = U2[k * G2 + gi * H2 + j];
    }
    if (i < G1 * 3 * FF) {   // Wt1[n][kp], n in [0,512), kp in [0,192)
        int n = i / 192, kp = i - n * 192;
        int p = kp / FF, ks = kp - p * FF;
        float v = W1[ks * G1 + (n & 3) * H1 + (n >> 2)];
        __nv_bfloat16 h = __float2bfloat16(v);
        g_Wt1[i] = (p == 1) ? __float2bfloat16(v - __bfloat162float(h)) : h;
    }
    if (i < G2 * 3 * H1) {   // Wt2[n][kp], n in [0,256), kp in [0,384)
        int n = i / 384, kp = i - n * 384;
        int p = kp / H1, ks = kp - p * H1;
        float v = W2[ks * G2 + (n & 3) * H2 + (n >> 2)];
        __nv_bfloat16 h = __float2bfloat16(v);
        g_Wt2[i] = (p == 1) ? __float2bfloat16(v - __bfloat162float(h)) : h;
    }
}

// ---------------------------------------------------------------------------
// Tensor-core GEMM, 3-pass fp32-via-bf16 with FRAGMENT REUSE (proven R16).
// Per base-K chunk of 32: smem holds Ah, Al, Bh, Bl (each [128][40]bf16).
// acc += Ah*Bh + Al*Bh + Ah*Bl  (AlBl dropped, ~2^-16 rel).
// CTA 128(m) x 128(n), 256 thr = 8 warps, warp tile 64x32.
// ---------------------------------------------------------------------------
#define GMMA_SMEM (4 * 10240)   // Ah, Al, Bh, Bl = 40960 B

__global__ __launch_bounds__(256, 2) void gemm_mma(
    const float* __restrict__ A, const __nv_bfloat16* __restrict__ Wt,
    const float* __restrict__ bias, float* __restrict__ C,
    int sT, int sB, int K, int Kcat, int Ntot)
{
    extern __shared__ char smb[];
    __nv_bfloat16* Ash = (__nv_bfloat16*)(smb);             // [128][40]
    __nv_bfloat16* Asl = (__nv_bfloat16*)(smb + 10240);
    __nv_bfloat16* Bsh = (__nv_bfloat16*)(smb + 20480);
    __nv_bfloat16* Bsl = (__nv_bfloat16*)(smb + 30720);
    const int tid = threadIdx.x, lane = tid & 31, wid = tid >> 5;
    const int wm = wid & 1, wn = wid >> 1;
    const int grp = lane >> 2;          // 0..7
    const int qc  = lane & 3;           // 0..3
    const int mt = blockIdx.x << 7, nt = blockIdx.y << 7;

    float acc[4][4][4];
#pragma unroll
    for (int mi = 0; mi < 4; mi++)
#pragma unroll
        for (int ni = 0; ni < 4; ni++)
#pragma unroll
            for (int q = 0; q < 4; q++) acc[mi][ni][q] = 0.f;

    // loader coords
    const int r = tid >> 1, hf = tid & 1;       // A: row r, k-half hf
    const int bn = tid >> 1, s0 = tid & 1;      // B: row n, segment parity
    const int gm = mt + r;
    const int t0 = gm >> 9, b0 = gm & 511;
    const float* arow = A + (size_t)t0 * sT + (size_t)b0 * sB;
    const __nv_bfloat16* brow = Wt + (size_t)(nt + bn) * Kcat;

    const int nchunks = K >> 5;
    for (int c = 0; c < nchunks; c++) {
        {   // ---- A: 16 fp32 -> bf16 hi AND lo ----
            int ksrc = (c << 5) + (hf << 4);
            float4 v0 = *(const float4*)(arow + ksrc);
            float4 v1 = *(const float4*)(arow + ksrc + 4);
            float4 v2 = *(const float4*)(arow + ksrc + 8);
            float4 v3 = *(const float4*)(arow + ksrc + 12);
            float f[16] = {v0.x, v0.y, v0.z, v0.w, v1.x, v1.y, v1.z, v1.w,
                           v2.x, v2.y, v2.z, v2.w, v3.x, v3.y, v3.z, v3.w};
            unsigned oh[8], ol[8];
#pragma unroll
            for (int q = 0; q < 8; q++) {
                __nv_bfloat16 h0 = __float2bfloat16(f[2 * q]);
                __nv_bfloat16 h1 = __float2bfloat16(f[2 * q + 1]);
                __nv_bfloat16 l0 = __float2bfloat16(f[2 * q] - __bfloat162float(h0));
                __nv_bfloat16 l1 = __float2bfloat16(f[2 * q + 1] - __bfloat162float(h1));
                oh[q] = (unsigned)__bfloat16_as_ushort(h0) |
                        ((unsigned)__bfloat16_as_ushort(h1) << 16);
                ol[q] = (unsigned)__bfloat16_as_ushort(l0) |
                        ((unsigned)__bfloat16_as_ushort(l1) << 16);
            }
            uint4* dh = (uint4*)((char*)Ash + r * 80 + hf * 32);
            dh[0] = make_uint4(oh[0], oh[1], oh[2], oh[3]);
            dh[1] = make_uint4(oh[4], oh[5], oh[6], oh[7]);
            uint4* dl = (uint4*)((char*)Asl + r * 80 + hf * 32);
            dl[0] = make_uint4(ol[0], ol[1], ol[2], ol[3]);
            dl[1] = make_uint4(ol[4], ol[5], ol[6], ol[7]);
        }
        {   // ---- B: Wh rows at k'=c*32, Wl rows at k'=K+c*32 ----
            const __nv_bfloat16* sh = brow + (c << 5);
            const __nv_bfloat16* sl = brow + K + (c << 5);
#pragma unroll
            for (int s = 0; s < 2; s++) {
                int seg = s0 + (s << 1);   // 0..3
                *(uint4*)((char*)Bsh + bn * 80 + seg * 16) = *(const uint4*)(sh + (seg << 3));
                *(uint4*)((char*)Bsl + bn * 80 + seg * 16) = *(const uint4*)(sl + (seg << 3));
            }
        }
        __syncthreads();
#pragma unroll
        for (int ks = 0; ks < 2; ks++) {
            const int kofs = (ks << 4) + (qc << 1);
            uint32_t afh[4][4];
#pragma unroll
            for (int mi = 0; mi < 4; mi++) {
                const __nv_bfloat16* ar0 = Ash + (wm * 64 + mi * 16 + grp) * 40 + kofs;
                afh[mi][0] = *(const uint32_t*)(ar0);
                afh[mi][1] = *(const uint32_t*)(ar0 + 8 * 40);
                afh[mi][2] = *(const uint32_t*)(ar0 + 8);
                afh[mi][3] = *(const uint32_t*)(ar0 + 8 * 40 + 8);
            }
            uint32_t bfh[4][2];
#pragma unroll
            for (int ni = 0; ni < 4; ni++) {
                const __nv_bfloat16* br0 = Bsh + (wn * 32 + ni * 8 + grp) * 40 + kofs;
                bfh[ni][0] = *(const uint32_t*)(br0);
                bfh[ni][1] = *(const uint32_t*)(br0 + 8);
            }
            // pass 1: Ah * Bh
#pragma unroll
            for (int mi = 0; mi < 4; mi++)
#pragma unroll
                for (int ni = 0; ni < 4; ni++)
                    asm volatile(
                        "mma.sync.aligned.m16n8k16.row.col.f32.bf16.bf16.f32 "
                        "{%0,%1,%2,%3}, {%4,%5,%6,%7}, {%8,%9}, {%0,%1,%2,%3};"
                        : "+f"(acc[mi][ni][0]), "+f"(acc[mi][ni][1]),
                          "+f"(acc[mi][ni][2]), "+f"(acc[mi][ni][3])
                        : "r"(afh[mi][0]), "r"(afh[mi][1]), "r"(afh[mi][2]), "r"(afh[mi][3]),
                          "r"(bfh[ni][0]), "r"(bfh[ni][1]));
            // pass 2: Al * Bh (Bh reused)
            {
                uint32_t afl[4][4];
#pragma unroll
                for (int mi = 0; mi < 4; mi++) {
                    const __nv_bfloat16* ar0 = Asl + (wm * 64 + mi * 16 + grp) * 40 + kofs;
                    afl[mi][0] = *(const uint32_t*)(ar0);
                    afl[mi][1] = *(const uint32_t*)(ar0 + 8 * 40);
                    afl[mi][2] = *(const uint32_t*)(ar0 + 8);
                    afl[mi][3] = *(const uint32_t*)(ar0 + 8 * 40 + 8);
                }
#pragma unroll
                for (int mi = 0; mi < 4; mi++)
#pragma unroll
                    for (int ni = 0; ni < 4; ni++)
                        asm volatile(
                            "mma.sync.aligned.m16n8k16.row.col.f32.bf16.bf16.f32 "
                            "{%0,%1,%2,%3}, {%4,%5,%6,%7}, {%8,%9}, {%0,%1,%2,%3};"
                            : "+f"(acc[mi][ni][0]), "+f"(acc[mi][ni][1]),
                              "+f"(acc[mi][ni][2]), "+f"(acc[mi][ni][3])
                            : "r"(afl[mi][0]), "r"(afl[mi][1]), "r"(afl[mi][2]), "r"(afl[mi][3]),
                              "r"(bfh[ni][0]), "r"(bfh[ni][1]));
            }
            // pass 3: Ah * Bl (Ah reused)
            {
                uint32_t bfl[4][2];
#pragma unroll
                for (int ni = 0; ni < 4; ni++) {
                    const __nv_bfloat16* br0 = Bsl + (wn * 32 + ni * 8 + grp) * 40 + kofs;
                    bfl[ni][0] = *(const uint32_t*)(br0);
                    bfl[ni][1] = *(const uint32_t*)(br0 + 8);
                }
#pragma unroll
                for (int mi = 0; mi < 4; mi++)
#pragma unroll
                    for (int ni = 0; ni < 4; ni++)
                        asm volatile(
                            "mma.sync.aligned.m16n8k16.row.col.f32.bf16.bf16.f32 "
                            "{%0,%1,%2,%3}, {%4,%5,%6,%7}, {%8,%9}, {%0,%1,%2,%3};"
                            : "+f"(acc[mi][ni][0]), "+f"(acc[mi][ni][1]),
                              "+f"(acc[mi][ni][2]), "+f"(acc[mi][ni][3])
                            : "r"(afh[mi][0]), "r"(afh[mi][1]), "r"(afh[mi][2]), "r"(afh[mi][3]),
                              "r"(bfl[ni][0]), "r"(bfl[ni][1]));
            }
        }
        __syncthreads();
    }

    // ---- epilogue: canonical C fragment ----
#pragma unroll
    for (int mi = 0; mi < 4; mi++) {
        int r0 = mt + wm * 64 + mi * 16 + grp;
#pragma unroll
        for (int ni = 0; ni < 4; ni++) {
            int col = nt + wn * 32 + ni * 8 + (qc << 1);
            float b0v = __ldg(bias + col), b1v = __ldg(bias + col + 1);
            *(float2*)(C + (size_t)r0 * Ntot + col) =
                make_float2(acc[mi][ni][0] + b0v, acc[mi][ni][1] + b1v);
            *(float2*)(C + (size_t)(r0 + 8) * Ntot + col) =
                make_float2(acc[mi][ni][2] + b0v, acc[mi][ni][3] + b1v);
        }
    }
}

// ---------------------------------------------------------------------------
// Layer-1 recurrence (proven R12/R4). 128 CTAs x 256 threads; CTA owns 4
// batch rows. thread = (j, ks in {0,1}); ks splits K=128. Per ks-half: 32 U
// rows in smem, 32 in registers. h as dup pairs {h,h} in smem.
// ---------------------------------------------------------------------------
#define REC1_SMEM ((64 * 512 + 2 * 128 * 8 + 128 * 20) * 4)  // 149504 B

__global__ __launch_bounds__(256, 1) void rec1_kernel()
{
    extern __shared__ float sm[];
    float* Us = sm;                  // [64][512]
    float* hd = sm + 64 * 512;       // [2][128][8]
    float* ex = hd + 2 * 128 * 8;    // [128][20]

    const int tid  = threadIdx.x;
    const int j    = tid & 127;
    const int ks   = tid >> 7;
    const int brow = blockIdx.x << 2;

    for (int i = tid; i < 64 * 128; i += 256) {
        int s = i >> 7;
        int c = (i & 127) << 2;
        int krow = (s < 32) ? s : (s + 32);
        *(float4*)(Us + s * 512 + c) = *(const float4*)(g_Up1 + krow * 512 + c);
    }
    const int rbase = ks * 64 + 32;
    ulonglong2 uw[32];
#pragma unroll
    for (int r = 0; r < 32; r++)
        uw[r] = *(const ulonglong2*)(g_Up1 + (rbase + r) * 512 + (j << 2));
    for (int i = tid; i < 2 * 128 * 8; i += 256) hd[i] = 0.f;
    float cc[4] = {0.f, 0.f, 0.f, 0.f};
    __syncthreads();

    const float* up0 = Us + (ks * 32) * 512 + (j << 2);
    int buf = 0;
    for (int t = 0; t < TT; t++) {
        u64 z2[4][2];
#pragma unroll
        for (int b = 0; b < 4; b++) { z2[b][0] = 0ull; z2[b][1] = 0ull; }

        ulonglong2 xv[4];
        if (ks == 0) {
#pragma unroll
            for (int b = 0; b < 4; b++)
                xv[b] = *(const ulonglong2*)(g_xw1 + ((size_t)(t * BB + brow + b) << 9) + (j << 2));
        }

        const float* hb = hd + buf * 1024;
        {
            const float* hp = hb + (ks * 64) * 8;
            const float* up = up0;
#pragma unroll 4
            for (int r = 0; r < 32; r++) {
                ulonglong2 hA = *(const ulonglong2*)(hp + (r << 3));
                ulonglong2 hB = *(const ulonglong2*)(hp + (r << 3) + 4);
                ulonglong2 uv = *(const ulonglong2*)(up);
                up += 512;
                fma2(z2[0][0], hA.x, uv.x); fma2(z2[0][1], hA.x, uv.y);
                fma2(z2[1][0], hA.y, uv.x); fma2(z2[1][1], hA.y, uv.y);
                fma2(z2[2][0], hB.x, uv.x); fma2(z2[2][1], hB.x, uv.y);
                fma2(z2[3][0], hB.y, uv.x); fma2(z2[3][1], hB.y, uv.y);
            }
        }
        {
            const float* hp = hb + rbase * 8;
#pragma unroll
            for (int r = 0; r < 32; r++) {
                ulonglong2 hA = *(const ulonglong2*)(hp + (r << 3));
                ulonglong2 hB = *(const ulonglong2*)(hp + (r << 3) + 4);
                fma2(z2[0][0], hA.x, uw[r].x); fma2(z2[0][1], hA.x, uw[r].y);
                fma2(z2[1][0], hA.y, uw[r].x); fma2(z2[1][1], hA.y, uw[r].y);
                fma2(z2[2][0], hB.x, uw[r].x); fma2(z2[2][1], hB.x, uw[r].y);
                fma2(z2[3][0], hB.y, uw[r].x); fma2(z2[3][1], hB.y, uw[r].y);
            }
        }
        if (ks) {
#pragma unroll
            for (int b = 0; b < 4; b++)
                *(ulonglong2*)(ex + j * 20 + (b << 2)) = make_ulonglong2(z2[b][0], z2[b][1]);
        }
        __syncthreads();
        if (ks == 0) {
            float* hn = hd + (buf ^ 1) * 1024;
            float hv[4];
#pragma unroll
            for (int b = 0; b < 4; b++) {
                ulonglong2 e = *(const ulonglong2*)(ex + j * 20 + (b << 2));
                add2(z2[b][0], e.x);
                add2(z2[b][1], e.y);
                add2(z2[b][0], xv[b].x);
                add2(z2[b][1], xv[b].y);
                float2 p0 = unpack2(z2[b][0]);
                float2 p1 = unpack2(z2[b][1]);
                float ig = sigf(p0.x);
                float fg = sigf(p0.y);
                float gg = fmaxf(p1.x, 0.f);
                float og = sigf(p1.y);
                cc[b] = fg * cc[b] + ig * gg;
                hv[b] = og * fmaxf(cc[b], 0.f);
                g_h1[((size_t)(t * BB + brow + b) << 7) + j] = hv[b];
            }
            *(ulonglong2*)(hn + (j << 3)) =
                make_ulonglong2(pack2(hv[0], hv[0]), pack2(hv[1], hv[1]));
            *(ulonglong2*)(hn + (j << 3) + 4) =
                make_ulonglong2(pack2(hv[2], hv[2]), pack2(hv[3], hv[3]));
        }
        __syncthreads();
        buf ^= 1;
    }
}

// ---------------------------------------------------------------------------
// Layer-2 recurrence (proven R12/R4), 4-way k-split. 128 CTAs x 256 threads.
// ---------------------------------------------------------------------------
#define REC2_SMEM ((32 * 256 + 2 * 64 * 8 + 3 * 64 * 20) * 4)  // 52480 B

__global__ __launch_bounds__(256, 1) void rec2_kernel()
{
    extern __shared__ float sm[];
    float* Us = sm;                  // [32][256]
    float* hd = sm + 32 * 256;       // [2][64][8]
    float* ex = hd + 2 * 64 * 8;     // [3][64][20]

    const int tid  = threadIdx.x;
    const int j    = tid & 63;
    const int ks   = tid >> 6;
    const int brow = blockIdx.x << 2;

    for (int i = tid; i < 32 * 64; i += 256) {
        int s = i >> 6;
        int c = (i & 63) << 2;
        int krow = ((s >> 3) << 4) + (s & 7);
        *(float4*)(Us + s * 256 + c) = *(const float4*)(g_Up2 + krow * 256 + c);
    }
    const int rbase = (ks << 4) + 8;
    ulonglong2 uw[8];
#pragma unroll
    for (int r = 0; r < 8; r++)
        uw[r] = *(const ulonglong2*)(g_Up2 + (rbase + r) * 256 + (j << 2));
    for (int i = tid; i < 2 * 64 * 8; i += 256) hd[i] = 0.f;
    float cc[4] = {0.f, 0.f, 0.f, 0.f};
    __syncthreads();

    const float* up0 = Us + (ks << 3) * 256 + (j << 2);
    int buf = 0;
    for (int t = 0; t < TT; t++) {
        u64 z2[4][2];
#pragma unroll
        for (int b = 0; b < 4; b++) { z2[b][0] = 0ull; z2[b][1] = 0ull; }

        ulonglong2 xv[4];
        if (ks == 0) {
#pragma unroll
            for (int b = 0; b < 4; b++)
                xv[b] = *(const ulonglong2*)(g_xw2 + ((size_t)(t * BB + brow + b) << 8) + (j << 2));
        }
        const float* hb = hd + buf * 512;
        {
            const float* hp = hb + (ks << 4) * 8;
            const float* up = up0;
#pragma unroll
            for (int r = 0; r < 8; r++) {
                ulonglong2 hA = *(const ulonglong2*)(hp + (r << 3));
                ulonglong2 hB = *(const ulonglong2*)(hp + (r << 3) + 4);
                ulonglong2 uv = *(const ulonglong2*)(up);
                up += 256;
                fma2(z2[0][0], hA.x, uv.x); fma2(z2[0][1], hA.x, uv.y);
                fma2(z2[1][0], hA.y, uv.x); fma2(z2[1][1], hA.y, uv.y);
                fma2(z2[2][0], hB.x, uv.x); fma2(z2[2][1], hB.x, uv.y);
                fma2(z2[3][0], hB.y, uv.x); fma2(z2[3][1], hB.y, uv.y);
            }
        }
        {
            const float* hp = hb + rbase * 8;
#pragma unroll
            for (int r = 0; r < 8; r++) {
                ulonglong2 hA = *(const ulonglong2*)(hp + (r << 3));
                ulonglong2 hB = *(const ulonglong2*)(hp + (r << 3) + 4);
                fma2(z2[0][0], hA.x, uw[r].x); fma2(z2[0][1], hA.x, uw[r].y);
                fma2(z2[1][0], hA.y, uw[r].x); fma2(z2[1][1], hA.y, uw[r].y);
                fma2(z2[2][0], hB.x, uw[r].x); fma2(z2[2][1], hB.x, uw[r].y);
                fma2(z2[3][0], hB.y, uw[r].x); fma2(z2[3][1], hB.y, uw[r].y);
            }
        }
        if (ks) {
            float* exq = ex + (ks - 1) * 1280 + j * 20;
#pragma unroll
            for (int b = 0; b < 4; b++)
                *(ulonglong2*)(exq + (b << 2)) = make_ulonglong2(z2[b][0], z2[b][1]);
        }
        __syncthreads();
        if (ks == 0) {
            float* hn = hd + (buf ^ 1) * 512;
            float hv[4];
#pragma unroll
            for (int b = 0; b < 4; b++) {
#pragma unroll
                for (int p = 0; p < 3; p++) {
                    ulonglong2 e = *(const ulonglong2*)(ex + p * 1280 + j * 20 + (b << 2));
                    add2(z2[b][0], e.x);
                    add2(z2[b][1], e.y);
                }
                add2(z2[b][0], xv[b].x);
                add2(z2[b][1], xv[b].y);
                float2 p0 = unpack2(z2[b][0]);
                float2 p1 = unpack2(z2[b][1]);
                float ig = sigf(p0.x);
                float fg = sigf(p0.y);
                float gg = fmaxf(p1.x, 0.f);
                float og = sigf(p1.y);
                cc[b] = fg * cc[b] + ig * gg;
                hv[b] = og * fmaxf(cc[b], 0.f);
                if (t == TT - 1)
                    g_h2[((brow + b) << 6) + j] = hv[b];
            }
            *(ulonglong2*)(hn + (j << 3)) =
                make_ulonglong2(pack2(hv[0], hv[0]), pack2(hv[1], hv[1]));
            *(ulonglong2*)(hn + (j << 3) + 4) =
                make_ulonglong2(pack2(hv[2], hv[2]), pack2(hv[3], hv[3]));
        }
        __syncthreads();
        buf ^= 1;
    }
}

// ---------------------------------------------------------------------------
// Dense head
// ---------------------------------------------------------------------------
__global__ void dense_kernel(const float* __restrict__ Wd1, const float* __restrict__ bd1,
                             const float* __restrict__ Wd2, const float* __restrict__ bd2,
                             float* __restrict__ out)
{
    int b = blockIdx.x * blockDim.x + threadIdx.x;
    if (b >= BB) return;
    float h[H2];
#pragma unroll
    for (int k = 0; k < H2; k++) h[k] = g_h2[(b << 6) + k];
    float acc = bd2[0];
    for (int d = 0; d < 25; d++) {
        float s = bd1[d];
#pragma unroll
        for (int k = 0; k < H2; k++) s += h[k] * Wd1[k * 25 + d];
        acc += s * Wd2[d];
    }
    out[b] = acc;
}

// ---------------------------------------------------------------------------
// Launch
// ---------------------------------------------------------------------------
extern "C" void kernel_launch(void* const* d_in, const int* in_sizes, int n_in,
                              void* d_out, int out_size)
{
    const float* x   = (const float*)d_in[0];
    const float* W1  = (const float*)d_in[1];
    const float* U1  = (const float*)d_in[2];
    const float* b1  = (const float*)d_in[3];
    const float* W2  = (const float*)d_in[4];
    const float* U2  = (const float*)d_in[5];
    const float* b2  = (const float*)d_in[6];
    const float* Wd1 = (const float*)d_in[7];
    const float* bd1 = (const float*)d_in[8];
    const float* Wd2 = (const float*)d_in[9];
    const float* bd2 = (const float*)d_in[10];
    float* out = (float*)d_out;

    cudaFuncSetAttribute(rec1_kernel, cudaFuncAttributeMaxDynamicSharedMemorySize, REC1_SMEM);
    cudaFuncSetAttribute(rec2_kernel, cudaFuncAttributeMaxDynamicSharedMemorySize, REC2_SMEM);

    float *pbp1, *pbp2, *pxw1, *pxw2, *ph1;
    void *pWt1, *pWt2;
    cudaGetSymbolAddress((void**)&pbp1, g_bp1);
    cudaGetSymbolAddress((void**)&pbp2, g_bp2);
    cudaGetSymbolAddress((void**)&pxw1, g_xw1);
    cudaGetSymbolAddress((void**)&pxw2, g_xw2);
    cudaGetSymbolAddress((void**)&ph1,  g_h1);
    cudaGetSymbolAddress(&pWt1, g_Wt1);
    cudaGetSymbolAddress(&pWt2, g_Wt2);

    // 1. weight permute + transposed stacked-K bf16 images
    prep_kernel<<<512, 256>>>(W1, U1, b1, W2, U2, b2);

    // 2. xW1 (tensor cores, 3-pass): x @ W1 -> g_xw1[t][b][:]
    gemm_mma<<<dim3((TT * BB) / 128, G1 / 128), 256, GMMA_SMEM>>>(
        x, (const __nv_bfloat16*)pWt1, pbp1, pxw1, FF, TT * FF, FF, 3 * FF, G1);

    // 3. layer-1 recurrence -> g_h1[t][b][:]
    rec1_kernel<<<BB / 4, 256, REC1_SMEM>>>();

    // 4. xW2 (tensor cores, 3-pass): h1 @ W2 -> g_xw2[t][b][:]
    gemm_mma<<<dim3((TT * BB) / 128, G2 / 128), 256, GMMA_SMEM>>>(
        ph1, (const __nv_bfloat16*)pWt2, pbp2, pxw2, BB * H1, H1, H1, 3 * H1, G2);

    // 5. layer-2 recurrence -> g_h2[b][:]
    rec2_kernel<<<BB / 4, 256, REC2_SMEM>>>();

    // 6. dense head
    dense_kernel<<<2, 256>>>(Wd1, bd1, Wd2, bd2, out);
}